// round 1
// baseline (speedup 1.0000x reference)
#include <cuda_runtime.h>
#include <cuda_bf16.h>
#include <cstddef>

// Problem dims (fixed)
#define BB 4
#define SS 2048
#define DD 1024
#define HH 16
#define HD 64
#define RR 512
#define MTOT (BB*SS)          // 8192 rows

// ---------------- scratch (device globals: allocation-guard safe) -------------
__device__ float g_q  [(size_t)MTOT * DD];   // 32 MB
__device__ float g_k  [(size_t)MTOT * DD];   // 32 MB
__device__ float g_v  [(size_t)MTOT * DD];   // 32 MB
__device__ float g_tmp[(size_t)MTOT * RR];   // 16 MB (reused for K and V low-rank)
__device__ float g_att[(size_t)MTOT * DD];   // 32 MB

// ---------------- GEMM: C[M,N] = A[M,K] @ op(W) + bias ------------------------
// TRANSW=true : W is [N,K] (nn.Linear weight), C = A @ W^T
// TRANSW=false: W is [K,N] (HF Conv1D),       C = A @ W
#define BM 128
#define BN 128
#define BK 16

template <bool TRANSW, bool BIAS>
__global__ void __launch_bounds__(256)
gemm_kernel(const float* __restrict__ A, const float* __restrict__ W,
            const float* __restrict__ bias, float* __restrict__ C,
            int M, int N, int K)
{
    __shared__ float As[BK][BM];
    __shared__ float Bs[BK][BN];

    const int tid = threadIdx.x;
    const int bm = blockIdx.y * BM;
    const int bn = blockIdx.x * BN;
    const int ty = tid >> 4;        // 0..15
    const int tx = tid & 15;        // 0..15

    float acc[8][8];
#pragma unroll
    for (int i = 0; i < 8; i++)
#pragma unroll
        for (int j = 0; j < 8; j++) acc[i][j] = 0.f;

    for (int k0 = 0; k0 < K; k0 += BK) {
        // load A tile (128x16), transpose into As[k][m]
#pragma unroll
        for (int i = tid; i < (BM * BK / 4); i += 256) {
            int row = i >> 2;
            int kc  = (i & 3) << 2;
            float4 a = *reinterpret_cast<const float4*>(
                &A[(size_t)(bm + row) * K + k0 + kc]);
            As[kc + 0][row] = a.x;
            As[kc + 1][row] = a.y;
            As[kc + 2][row] = a.z;
            As[kc + 3][row] = a.w;
        }
        if (TRANSW) {
            // W[N,K]: load rows of W, transpose into Bs[k][n]
#pragma unroll
            for (int i = tid; i < (BN * BK / 4); i += 256) {
                int row = i >> 2;
                int kc  = (i & 3) << 2;
                float4 w = *reinterpret_cast<const float4*>(
                    &W[(size_t)(bn + row) * K + k0 + kc]);
                Bs[kc + 0][row] = w.x;
                Bs[kc + 1][row] = w.y;
                Bs[kc + 2][row] = w.z;
                Bs[kc + 3][row] = w.w;
            }
        } else {
            // W[K,N]: direct copy rows into Bs[k][n]
#pragma unroll
            for (int i = tid; i < (BK * BN / 4); i += 256) {
                int kr = i >> 5;
                int nc = (i & 31) << 2;
                float4 w = *reinterpret_cast<const float4*>(
                    &W[(size_t)(k0 + kr) * N + bn + nc]);
                *reinterpret_cast<float4*>(&Bs[kr][nc]) = w;
            }
        }
        __syncthreads();

#pragma unroll
        for (int kk = 0; kk < BK; kk++) {
            float a[8], b[8];
            *reinterpret_cast<float4*>(&a[0]) =
                *reinterpret_cast<const float4*>(&As[kk][ty * 8]);
            *reinterpret_cast<float4*>(&a[4]) =
                *reinterpret_cast<const float4*>(&As[kk][ty * 8 + 4]);
            *reinterpret_cast<float4*>(&b[0]) =
                *reinterpret_cast<const float4*>(&Bs[kk][tx * 8]);
            *reinterpret_cast<float4*>(&b[4]) =
                *reinterpret_cast<const float4*>(&Bs[kk][tx * 8 + 4]);
#pragma unroll
            for (int i = 0; i < 8; i++)
#pragma unroll
                for (int j = 0; j < 8; j++)
                    acc[i][j] += a[i] * b[j];
        }
        __syncthreads();
    }

    // epilogue
#pragma unroll
    for (int i = 0; i < 8; i++) {
        const size_t row = (size_t)(bm + ty * 8 + i);
#pragma unroll
        for (int j = 0; j < 8; j += 4) {
            float4 r;
            int col = bn + tx * 8 + j;
            r.x = acc[i][j + 0] + (BIAS ? bias[col + 0] : 0.f);
            r.y = acc[i][j + 1] + (BIAS ? bias[col + 1] : 0.f);
            r.z = acc[i][j + 2] + (BIAS ? bias[col + 2] : 0.f);
            r.w = acc[i][j + 3] + (BIAS ? bias[col + 3] : 0.f);
            *reinterpret_cast<float4*>(&C[row * N + col]) = r;
        }
    }
}

// ---------------- causal flash attention (fp32) -------------------------------
// grid: (S/64, H, B), block: 256 threads, dynamic smem.
// q/k/v layouts: [B,S,D] with head h at columns [h*64, h*64+64).
// out layout: [B,S,D] merged bqhd (same as q).
#define ALD 65   // smem row pitch (padding: keeps conflicts <= 2-way)

__global__ void __launch_bounds__(256)
attn_kernel(const float* __restrict__ Q, const float* __restrict__ Kg,
            const float* __restrict__ Vg, float* __restrict__ O)
{
    extern __shared__ float sm[];
    float* Qs   = sm;                 // 64*ALD
    float* Ks   = Qs + 64 * ALD;      // 64*ALD
    float* Vs   = Ks + 64 * ALD;      // 64*ALD
    float* Ps   = Vs + 64 * ALD;      // 64*ALD
    float* mrow = Ps + 64 * ALD;      // 64
    float* lrow = mrow + 64;          // 64
    float* srow = lrow + 64;          // 64
    float* red  = srow + 64;          // 256

    const int qt = blockIdx.x;
    const int h  = blockIdx.y;
    const int b  = blockIdx.z;
    const int tid = threadIdx.x;
    const int ty = tid >> 4;          // 0..15
    const int tx = tid & 15;          // 0..15
    const int rr = tid >> 2;          // 0..63 (row for softmax passes)
    const int qd = tid & 3;           // quarter

    const float* qbase = Q + ((size_t)b * SS + (size_t)qt * 64) * DD + h * HD;

    // load Q tile (64 x 64)
    for (int i = tid; i < 1024; i += 256) {
        int r = i >> 4;
        int d = (i & 15) << 2;
        float4 t = *reinterpret_cast<const float4*>(&qbase[(size_t)r * DD + d]);
        Qs[r * ALD + d + 0] = t.x;
        Qs[r * ALD + d + 1] = t.y;
        Qs[r * ALD + d + 2] = t.z;
        Qs[r * ALD + d + 3] = t.w;
    }
    if (tid < 64) { mrow[tid] = -1e30f; lrow[tid] = 0.f; }

    float o[4][4];
#pragma unroll
    for (int i = 0; i < 4; i++)
#pragma unroll
        for (int j = 0; j < 4; j++) o[i][j] = 0.f;

    for (int kt = 0; kt <= qt; kt++) {
        const float* kbase = Kg + ((size_t)b * SS + (size_t)kt * 64) * DD + h * HD;
        const float* vbase = Vg + ((size_t)b * SS + (size_t)kt * 64) * DD + h * HD;

        __syncthreads();   // protect smem from previous iteration / Q load done
        for (int i = tid; i < 1024; i += 256) {
            int r = i >> 4;
            int d = (i & 15) << 2;
            float4 t = *reinterpret_cast<const float4*>(&kbase[(size_t)r * DD + d]);
            Ks[r * ALD + d + 0] = t.x;
            Ks[r * ALD + d + 1] = t.y;
            Ks[r * ALD + d + 2] = t.z;
            Ks[r * ALD + d + 3] = t.w;
            float4 u = *reinterpret_cast<const float4*>(&vbase[(size_t)r * DD + d]);
            Vs[r * ALD + d + 0] = u.x;
            Vs[r * ALD + d + 1] = u.y;
            Vs[r * ALD + d + 2] = u.z;
            Vs[r * ALD + d + 3] = u.w;
        }
        __syncthreads();

        // S = (Q K^T) * 1/sqrt(64)
        float s[4][4];
#pragma unroll
        for (int i = 0; i < 4; i++)
#pragma unroll
            for (int j = 0; j < 4; j++) s[i][j] = 0.f;

#pragma unroll 8
        for (int d = 0; d < 64; d++) {
            float qa[4], kb[4];
#pragma unroll
            for (int i = 0; i < 4; i++) qa[i] = Qs[(ty * 4 + i) * ALD + d];
#pragma unroll
            for (int j = 0; j < 4; j++) kb[j] = Ks[(tx * 4 + j) * ALD + d];
#pragma unroll
            for (int i = 0; i < 4; i++)
#pragma unroll
                for (int j = 0; j < 4; j++)
                    s[i][j] += qa[i] * kb[j];
        }
#pragma unroll
        for (int i = 0; i < 4; i++)
#pragma unroll
            for (int j = 0; j < 4; j++) {
                float v = s[i][j] * 0.125f;
                if (kt == qt && (tx * 4 + j) > (ty * 4 + i)) v = -1e30f;
                Ps[(ty * 4 + i) * ALD + tx * 4 + j] = v;
            }
        __syncthreads();

        // pass A: partial row max
        {
            float mx = -1e30f;
            for (int c = qd * 16; c < qd * 16 + 16; c++)
                mx = fmaxf(mx, Ps[rr * ALD + c]);
            red[rr * 4 + qd] = mx;
        }
        __syncthreads();
        if (tid < 64) {
            float mo = mrow[tid];
            float mn = fmaxf(fmaxf(red[tid * 4], red[tid * 4 + 1]),
                             fmaxf(red[tid * 4 + 2], red[tid * 4 + 3]));
            mn = fmaxf(mo, mn);
            srow[tid] = __expf(mo - mn);
            mrow[tid] = mn;
        }
        __syncthreads();

        // pass B: exponentiate + partial row sum
        {
            float mn = mrow[rr];
            float sum = 0.f;
            for (int c = qd * 16; c < qd * 16 + 16; c++) {
                float p = __expf(Ps[rr * ALD + c] - mn);
                Ps[rr * ALD + c] = p;
                sum += p;
            }
            red[rr * 4 + qd] = sum;
        }
        __syncthreads();
        if (tid < 64) {
            lrow[tid] = lrow[tid] * srow[tid] +
                        red[tid * 4] + red[tid * 4 + 1] +
                        red[tid * 4 + 2] + red[tid * 4 + 3];
        }

        // O = O*scale + P V
        float sci[4];
#pragma unroll
        for (int i = 0; i < 4; i++) sci[i] = srow[ty * 4 + i];
#pragma unroll
        for (int i = 0; i < 4; i++)
#pragma unroll
            for (int j = 0; j < 4; j++) o[i][j] *= sci[i];

#pragma unroll 8
        for (int c = 0; c < 64; c++) {
            float pa[4], vb[4];
#pragma unroll
            for (int i = 0; i < 4; i++) pa[i] = Ps[(ty * 4 + i) * ALD + c];
#pragma unroll
            for (int j = 0; j < 4; j++) vb[j] = Vs[c * ALD + tx * 4 + j];
#pragma unroll
            for (int i = 0; i < 4; i++)
#pragma unroll
                for (int j = 0; j < 4; j++)
                    o[i][j] += pa[i] * vb[j];
        }
    }
    __syncthreads();   // lrow final values visible

    float* obase = O + ((size_t)b * SS + (size_t)qt * 64) * DD + h * HD;
#pragma unroll
    for (int i = 0; i < 4; i++) {
        float inv = 1.0f / lrow[ty * 4 + i];
#pragma unroll
        for (int j = 0; j < 4; j++)
            obase[(size_t)(ty * 4 + i) * DD + tx * 4 + j] = o[i][j] * inv;
    }
}

// ---------------- launch ------------------------------------------------------
extern "C" void kernel_launch(void* const* d_in, const int* in_sizes, int n_in,
                              void* d_out, int out_size)
{
    const float* hs     = (const float*)d_in[0];
    const float* WQ_w   = (const float*)d_in[1];
    const float* WQ_b   = (const float*)d_in[2];
    const float* WK_A_w = (const float*)d_in[3];
    const float* WK_B_w = (const float*)d_in[4];
    const float* WK_B_b = (const float*)d_in[5];
    const float* WV_A_w = (const float*)d_in[6];
    const float* WV_B_w = (const float*)d_in[7];
    const float* WV_B_b = (const float*)d_in[8];
    const float* c_w    = (const float*)d_in[9];
    const float* c_b    = (const float*)d_in[10];
    float* out = (float*)d_out;

    float *gq, *gk, *gv, *gtmp, *gatt;
    cudaGetSymbolAddress((void**)&gq,   g_q);
    cudaGetSymbolAddress((void**)&gk,   g_k);
    cudaGetSymbolAddress((void**)&gv,   g_v);
    cudaGetSymbolAddress((void**)&gtmp, g_tmp);
    cudaGetSymbolAddress((void**)&gatt, g_att);

    const int smem_attn = (4 * 64 * ALD + 3 * 64 + 256) * (int)sizeof(float);
    cudaFuncSetAttribute(attn_kernel,
                         cudaFuncAttributeMaxDynamicSharedMemorySize, smem_attn);

    dim3 blk(256);

    // Q = hs @ WQ^T + b          [8192,1024]
    gemm_kernel<true, true><<<dim3(DD / BN, MTOT / BM), blk>>>(
        hs, WQ_w, WQ_b, gq, MTOT, DD, DD);

    // K = (hs @ WK_A^T) @ WK_B^T + b
    gemm_kernel<true, false><<<dim3(RR / BN, MTOT / BM), blk>>>(
        hs, WK_A_w, nullptr, gtmp, MTOT, RR, DD);
    gemm_kernel<true, true><<<dim3(DD / BN, MTOT / BM), blk>>>(
        gtmp, WK_B_w, WK_B_b, gk, MTOT, DD, RR);

    // V = (hs @ WV_A^T) @ WV_B^T + b
    gemm_kernel<true, false><<<dim3(RR / BN, MTOT / BM), blk>>>(
        hs, WV_A_w, nullptr, gtmp, MTOT, RR, DD);
    gemm_kernel<true, true><<<dim3(DD / BN, MTOT / BM), blk>>>(
        gtmp, WV_B_w, WV_B_b, gv, MTOT, DD, RR);

    // causal attention
    attn_kernel<<<dim3(SS / 64, HH, BB), blk, smem_attn>>>(gq, gk, gv, gatt);

    // out = att @ c_proj_w + c_proj_b   (Conv1D: W is [in,out])
    gemm_kernel<false, true><<<dim3(DD / BN, MTOT / BM), blk>>>(
        gatt, c_w, c_b, out, MTOT, DD, DD);

    (void)in_sizes; (void)n_in; (void)out_size;
}

// round 4
// speedup vs baseline: 1.5520x; 1.5520x over previous
#include <cuda_runtime.h>
#include <cuda_bf16.h>
#include <cstdint>
#include <cstddef>

// Problem dims (fixed)
#define BB 4
#define SS 2048
#define DD 1024
#define HH 16
#define HD 64
#define RR 512
#define MTOT (BB*SS)          // 8192 rows

// ---------------- scratch (device globals: allocation-guard safe) -------------
__device__ float g_q  [(size_t)MTOT * DD];   // 32 MB
__device__ float g_k  [(size_t)MTOT * DD];   // 32 MB
__device__ float g_v  [(size_t)MTOT * DD];   // 32 MB
__device__ float g_att[(size_t)MTOT * DD];   // 32 MB
__device__ float g_tmp[(size_t)MTOT * RR];   // 16 MB
__device__ float g_cpt[(size_t)DD * DD];     // 4 MB  (c_proj transposed -> [N,K])

// ---------------- mma.sync helpers (family-stable, OK on compute_103) ----------
__device__ __forceinline__ uint32_t smem_u32(const void* p) {
    uint32_t a;
    asm("{ .reg .u64 t; cvta.to.shared.u64 t, %1; cvt.u32.u64 %0, t; }"
        : "=r"(a) : "l"(p));
    return a;
}

__device__ __forceinline__ void ldsm_x4(uint32_t addr, uint32_t* r) {
    asm volatile("ldmatrix.sync.aligned.m8n8.x4.shared.b16 {%0,%1,%2,%3}, [%4];"
                 : "=r"(r[0]), "=r"(r[1]), "=r"(r[2]), "=r"(r[3]) : "r"(addr));
}
__device__ __forceinline__ void mma16816(float* d, const uint32_t* a, const uint32_t* b) {
    asm volatile(
        "mma.sync.aligned.m16n8k16.row.col.f32.bf16.bf16.f32 "
        "{%0,%1,%2,%3}, {%4,%5,%6,%7}, {%8,%9}, {%0,%1,%2,%3};"
        : "+f"(d[0]), "+f"(d[1]), "+f"(d[2]), "+f"(d[3])
        : "r"(a[0]), "r"(a[1]), "r"(a[2]), "r"(a[3]), "r"(b[0]), "r"(b[1]));
}

// split a float4 into packed-bf16 hi(8B) and lo(8B)
__device__ __forceinline__ void split_f4(float4 v, uint2& hi, uint2& lo) {
    __nv_bfloat16 h0 = __float2bfloat16(v.x), h1 = __float2bfloat16(v.y);
    __nv_bfloat16 h2 = __float2bfloat16(v.z), h3 = __float2bfloat16(v.w);
    __nv_bfloat16 l0 = __float2bfloat16(v.x - __bfloat162float(h0));
    __nv_bfloat16 l1 = __float2bfloat16(v.y - __bfloat162float(h1));
    __nv_bfloat16 l2 = __float2bfloat16(v.z - __bfloat162float(h2));
    __nv_bfloat16 l3 = __float2bfloat16(v.w - __bfloat162float(h3));
    __nv_bfloat162 hp0(h0, h1), hp1(h2, h3), lp0(l0, l1), lp1(l2, l3);
    hi.x = *reinterpret_cast<uint32_t*>(&hp0);
    hi.y = *reinterpret_cast<uint32_t*>(&hp1);
    lo.x = *reinterpret_cast<uint32_t*>(&lp0);
    lo.y = *reinterpret_cast<uint32_t*>(&lp1);
}

// ---------------- HMMA bf16x3 GEMM ---------------------------------------------
// C[M,N] = A[M,K] @ B[N,K]^T (+ bias). fp32 I/O, bf16 hi/lo split on the fly.
// 128x128 tile, BK=32, 8 warps (4M x 2N), warp tile 32x64, double-buffered smem.
#define PITCH 80                 // bytes per 32-bf16 row (64B data + 16B pad)
#define TILE_B (128 * PITCH)     // 10240 B per matrix tile
#define STAGE_B (4 * TILE_B)     // Ahi, Alo, Bhi, Blo
#define HMMA_SMEM (2 * STAGE_B)  // 81920 B

template <bool BIAS>
__global__ void __launch_bounds__(256)
hmma_gemm(const float* __restrict__ A, const float* __restrict__ B,
          const float* __restrict__ bias, float* __restrict__ C,
          int M, int N, int K)
{
    extern __shared__ char smem[];
    const uint32_t sb = smem_u32(smem);

    const int tid  = threadIdx.x;
    const int lane = tid & 31;
    const int wid  = tid >> 5;
    const int m0 = blockIdx.y * 128, n0 = blockIdx.x * 128;
    const int wm = (wid & 3) * 32;      // warp M offset in tile
    const int wn = (wid >> 2) * 64;     // warp N offset in tile

    // loader indexing: thread covers rows (tid>>3)+32p, float4 q = tid&7
    const int lr = tid >> 3;
    const int lq = tid & 7;

    // ldmatrix per-thread address components (A and B both [row][k], non-trans)
    const int a_row = wm + (lane & 7) + ((lane >> 3) & 1) * 8;   // + mt*16
    const int a_kb  = ((lane >> 4) & 1) * 16;
    const int b_row = wn + (lane & 7) + ((lane >> 4) & 1) * 8;   // + nt2*16
    const int b_kb  = ((lane >> 3) & 1) * 16;

    float acc[2][8][4];
#pragma unroll
    for (int i = 0; i < 2; i++)
#pragma unroll
        for (int j = 0; j < 8; j++)
#pragma unroll
            for (int k = 0; k < 4; k++) acc[i][j][k] = 0.f;

    const int NC = K >> 5;   // chunks of 32

    float4 ra[4], rb[4];
    // prologue: chunk 0
#pragma unroll
    for (int p = 0; p < 4; p++) {
        int row = lr + p * 32;
        ra[p] = *reinterpret_cast<const float4*>(&A[(size_t)(m0 + row) * K + lq * 4]);
        rb[p] = *reinterpret_cast<const float4*>(&B[(size_t)(n0 + row) * K + lq * 4]);
    }
    {
#pragma unroll
        for (int p = 0; p < 4; p++) {
            int row = lr + p * 32;
            uint32_t off = (uint32_t)(row * PITCH + lq * 8);
            uint2 hi, lo;
            split_f4(ra[p], hi, lo);
            *reinterpret_cast<uint2*>(smem + (off))              = hi;
            *reinterpret_cast<uint2*>(smem + (off + TILE_B))     = lo;
            split_f4(rb[p], hi, lo);
            *reinterpret_cast<uint2*>(smem + (off + 2 * TILE_B)) = hi;
            *reinterpret_cast<uint2*>(smem + (off + 3 * TILE_B)) = lo;
        }
    }
    __syncthreads();

    for (int c = 0; c < NC; c++) {
        // prefetch next chunk to regs
        if (c + 1 < NC) {
            const int kc = (c + 1) << 5;
#pragma unroll
            for (int p = 0; p < 4; p++) {
                int row = lr + p * 32;
                ra[p] = *reinterpret_cast<const float4*>(
                    &A[(size_t)(m0 + row) * K + kc + lq * 4]);
                rb[p] = *reinterpret_cast<const float4*>(
                    &B[(size_t)(n0 + row) * K + kc + lq * 4]);
            }
        }

        // compute on current stage
        const uint32_t st = sb + (uint32_t)(c & 1) * STAGE_B;
#pragma unroll
        for (int ks = 0; ks < 2; ks++) {
            uint32_t ah[2][4], al[2][4];
#pragma unroll
            for (int mt = 0; mt < 2; mt++) {
                uint32_t aaddr = st + (uint32_t)((a_row + mt * 16) * PITCH + a_kb + ks * 32);
                ldsm_x4(aaddr, ah[mt]);
                ldsm_x4(aaddr + TILE_B, al[mt]);
            }
#pragma unroll
            for (int nt2 = 0; nt2 < 4; nt2++) {
                uint32_t bh[4], bl[4];
                uint32_t baddr = st + 2 * TILE_B +
                    (uint32_t)((b_row + nt2 * 16) * PITCH + b_kb + ks * 32);
                ldsm_x4(baddr, bh);           // FIXED: non-trans ([n][k] smem layout)
                ldsm_x4(baddr + TILE_B, bl);  // FIXED: non-trans
#pragma unroll
                for (int mt = 0; mt < 2; mt++) {
#pragma unroll
                    for (int half = 0; half < 2; half++) {
                        float* d = acc[mt][nt2 * 2 + half];
                        mma16816(d, ah[mt], &bh[half * 2]);
                        mma16816(d, ah[mt], &bl[half * 2]);
                        mma16816(d, al[mt], &bh[half * 2]);
                    }
                }
            }
        }

        // store next chunk into other stage
        if (c + 1 < NC) {
            char* so = smem + (size_t)((c + 1) & 1) * STAGE_B;
#pragma unroll
            for (int p = 0; p < 4; p++) {
                int row = lr + p * 32;
                uint32_t off = (uint32_t)(row * PITCH + lq * 8);
                uint2 hi, lo;
                split_f4(ra[p], hi, lo);
                *reinterpret_cast<uint2*>(so + off)              = hi;
                *reinterpret_cast<uint2*>(so + off + TILE_B)     = lo;
                split_f4(rb[p], hi, lo);
                *reinterpret_cast<uint2*>(so + off + 2 * TILE_B) = hi;
                *reinterpret_cast<uint2*>(so + off + 3 * TILE_B) = lo;
            }
        }
        __syncthreads();
    }

    // epilogue: acc -> C (+bias)
    const int g = lane >> 2;
    const int cpair = (lane & 3) * 2;
#pragma unroll
    for (int mt = 0; mt < 2; mt++) {
#pragma unroll
        for (int nt = 0; nt < 8; nt++) {
            int col = n0 + wn + nt * 8 + cpair;
            float bx = 0.f, by = 0.f;
            if (BIAS) { bx = bias[col]; by = bias[col + 1]; }
            int row0 = m0 + wm + mt * 16 + g;
            float2 v0 = make_float2(acc[mt][nt][0] + bx, acc[mt][nt][1] + by);
            float2 v1 = make_float2(acc[mt][nt][2] + bx, acc[mt][nt][3] + by);
            *reinterpret_cast<float2*>(&C[(size_t)row0 * N + col])       = v0;
            *reinterpret_cast<float2*>(&C[(size_t)(row0 + 8) * N + col]) = v1;
        }
    }
}

// ---------------- fp32 transpose (for c_proj: [K,N] -> [N,K]) ------------------
__global__ void __launch_bounds__(256)
transpose_kernel(const float* __restrict__ W, float* __restrict__ out, int K, int N)
{
    __shared__ float t[32][33];
    int k0 = blockIdx.y * 32, n0 = blockIdx.x * 32;
    int tx = threadIdx.x & 31, ty = threadIdx.x >> 5;   // 32 x 8
#pragma unroll
    for (int i = 0; i < 32; i += 8)
        t[ty + i][tx] = W[(size_t)(k0 + ty + i) * N + n0 + tx];
    __syncthreads();
#pragma unroll
    for (int i = 0; i < 32; i += 8)
        out[(size_t)(n0 + ty + i) * K + k0 + tx] = t[tx][ty + i];
}

// ---------------- causal flash attention (fp32 SIMT, known-correct) ------------
#define ALD 65

__global__ void __launch_bounds__(256)
attn_kernel(const float* __restrict__ Q, const float* __restrict__ Kg,
            const float* __restrict__ Vg, float* __restrict__ O)
{
    extern __shared__ float sm[];
    float* Qs   = sm;
    float* Ks   = Qs + 64 * ALD;
    float* Vs   = Ks + 64 * ALD;
    float* Ps   = Vs + 64 * ALD;
    float* mrow = Ps + 64 * ALD;
    float* lrow = mrow + 64;
    float* srow = lrow + 64;
    float* red  = srow + 64;

    const int qt = blockIdx.x;
    const int h  = blockIdx.y;
    const int b  = blockIdx.z;
    const int tid = threadIdx.x;
    const int ty = tid >> 4;
    const int tx = tid & 15;
    const int rr = tid >> 2;
    const int qd = tid & 3;

    const float* qbase = Q + ((size_t)b * SS + (size_t)qt * 64) * DD + h * HD;

    for (int i = tid; i < 1024; i += 256) {
        int r = i >> 4;
        int d = (i & 15) << 2;
        float4 t = *reinterpret_cast<const float4*>(&qbase[(size_t)r * DD + d]);
        Qs[r * ALD + d + 0] = t.x;
        Qs[r * ALD + d + 1] = t.y;
        Qs[r * ALD + d + 2] = t.z;
        Qs[r * ALD + d + 3] = t.w;
    }
    if (tid < 64) { mrow[tid] = -1e30f; lrow[tid] = 0.f; }

    float o[4][4];
#pragma unroll
    for (int i = 0; i < 4; i++)
#pragma unroll
        for (int j = 0; j < 4; j++) o[i][j] = 0.f;

    for (int kt = 0; kt <= qt; kt++) {
        const float* kbase = Kg + ((size_t)b * SS + (size_t)kt * 64) * DD + h * HD;
        const float* vbase = Vg + ((size_t)b * SS + (size_t)kt * 64) * DD + h * HD;

        __syncthreads();
        for (int i = tid; i < 1024; i += 256) {
            int r = i >> 4;
            int d = (i & 15) << 2;
            float4 t = *reinterpret_cast<const float4*>(&kbase[(size_t)r * DD + d]);
            Ks[r * ALD + d + 0] = t.x;
            Ks[r * ALD + d + 1] = t.y;
            Ks[r * ALD + d + 2] = t.z;
            Ks[r * ALD + d + 3] = t.w;
            float4 u = *reinterpret_cast<const float4*>(&vbase[(size_t)r * DD + d]);
            Vs[r * ALD + d + 0] = u.x;
            Vs[r * ALD + d + 1] = u.y;
            Vs[r * ALD + d + 2] = u.z;
            Vs[r * ALD + d + 3] = u.w;
        }
        __syncthreads();

        float s[4][4];
#pragma unroll
        for (int i = 0; i < 4; i++)
#pragma unroll
            for (int j = 0; j < 4; j++) s[i][j] = 0.f;

#pragma unroll 8
        for (int d = 0; d < 64; d++) {
            float qa[4], kb[4];
#pragma unroll
            for (int i = 0; i < 4; i++) qa[i] = Qs[(ty * 4 + i) * ALD + d];
#pragma unroll
            for (int j = 0; j < 4; j++) kb[j] = Ks[(tx * 4 + j) * ALD + d];
#pragma unroll
            for (int i = 0; i < 4; i++)
#pragma unroll
                for (int j = 0; j < 4; j++)
                    s[i][j] += qa[i] * kb[j];
        }
#pragma unroll
        for (int i = 0; i < 4; i++)
#pragma unroll
            for (int j = 0; j < 4; j++) {
                float v = s[i][j] * 0.125f;
                if (kt == qt && (tx * 4 + j) > (ty * 4 + i)) v = -1e30f;
                Ps[(ty * 4 + i) * ALD + tx * 4 + j] = v;
            }
        __syncthreads();

        {
            float mx = -1e30f;
            for (int c = qd * 16; c < qd * 16 + 16; c++)
                mx = fmaxf(mx, Ps[rr * ALD + c]);
            red[rr * 4 + qd] = mx;
        }
        __syncthreads();
        if (tid < 64) {
            float mo = mrow[tid];
            float mn = fmaxf(fmaxf(red[tid * 4], red[tid * 4 + 1]),
                             fmaxf(red[tid * 4 + 2], red[tid * 4 + 3]));
            mn = fmaxf(mo, mn);
            srow[tid] = __expf(mo - mn);
            mrow[tid] = mn;
        }
        __syncthreads();

        {
            float mn = mrow[rr];
            float sum = 0.f;
            for (int c = qd * 16; c < qd * 16 + 16; c++) {
                float p = __expf(Ps[rr * ALD + c] - mn);
                Ps[rr * ALD + c] = p;
                sum += p;
            }
            red[rr * 4 + qd] = sum;
        }
        __syncthreads();
        if (tid < 64) {
            lrow[tid] = lrow[tid] * srow[tid] +
                        red[tid * 4] + red[tid * 4 + 1] +
                        red[tid * 4 + 2] + red[tid * 4 + 3];
        }

        float sci[4];
#pragma unroll
        for (int i = 0; i < 4; i++) sci[i] = srow[ty * 4 + i];
#pragma unroll
        for (int i = 0; i < 4; i++)
#pragma unroll
            for (int j = 0; j < 4; j++) o[i][j] *= sci[i];

#pragma unroll 8
        for (int c = 0; c < 64; c++) {
            float pa[4], vb[4];
#pragma unroll
            for (int i = 0; i < 4; i++) pa[i] = Ps[(ty * 4 + i) * ALD + c];
#pragma unroll
            for (int j = 0; j < 4; j++) vb[j] = Vs[c * ALD + tx * 4 + j];
#pragma unroll
            for (int i = 0; i < 4; i++)
#pragma unroll
                for (int j = 0; j < 4; j++)
                    o[i][j] += pa[i] * vb[j];
        }
    }
    __syncthreads();

    float* obase = O + ((size_t)b * SS + (size_t)qt * 64) * DD + h * HD;
#pragma unroll
    for (int i = 0; i < 4; i++) {
        float inv = 1.0f / lrow[ty * 4 + i];
#pragma unroll
        for (int j = 0; j < 4; j++)
            obase[(size_t)(ty * 4 + i) * DD + tx * 4 + j] = o[i][j] * inv;
    }
}

// ---------------- launch ------------------------------------------------------
extern "C" void kernel_launch(void* const* d_in, const int* in_sizes, int n_in,
                              void* d_out, int out_size)
{
    const float* hs     = (const float*)d_in[0];
    const float* WQ_w   = (const float*)d_in[1];
    const float* WQ_b   = (const float*)d_in[2];
    const float* WK_A_w = (const float*)d_in[3];
    const float* WK_B_w = (const float*)d_in[4];
    const float* WK_B_b = (const float*)d_in[5];
    const float* WV_A_w = (const float*)d_in[6];
    const float* WV_B_w = (const float*)d_in[7];
    const float* WV_B_b = (const float*)d_in[8];
    const float* c_w    = (const float*)d_in[9];
    const float* c_b    = (const float*)d_in[10];
    float* out = (float*)d_out;

    float *gq, *gk, *gv, *gatt, *gtmp, *gcpt;
    cudaGetSymbolAddress((void**)&gq,   g_q);
    cudaGetSymbolAddress((void**)&gk,   g_k);
    cudaGetSymbolAddress((void**)&gv,   g_v);
    cudaGetSymbolAddress((void**)&gatt, g_att);
    cudaGetSymbolAddress((void**)&gtmp, g_tmp);
    cudaGetSymbolAddress((void**)&gcpt, g_cpt);

    cudaFuncSetAttribute(hmma_gemm<true>,
                         cudaFuncAttributeMaxDynamicSharedMemorySize, HMMA_SMEM);
    cudaFuncSetAttribute(hmma_gemm<false>,
                         cudaFuncAttributeMaxDynamicSharedMemorySize, HMMA_SMEM);
    const int smem_attn = (4 * 64 * ALD + 3 * 64 + 256) * (int)sizeof(float);
    cudaFuncSetAttribute(attn_kernel,
                         cudaFuncAttributeMaxDynamicSharedMemorySize, smem_attn);

    dim3 blk(256);

    // c_proj: [K,N] -> [N,K] once
    transpose_kernel<<<dim3(DD / 32, DD / 32), blk>>>(c_w, gcpt, DD, DD);

    // Q = hs @ WQ^T + b
    hmma_gemm<true><<<dim3(DD / 128, MTOT / 128), blk, HMMA_SMEM>>>(
        hs, WQ_w, WQ_b, gq, MTOT, DD, DD);
    // tmp = hs @ WK_A^T ; K = tmp @ WK_B^T + b
    hmma_gemm<false><<<dim3(RR / 128, MTOT / 128), blk, HMMA_SMEM>>>(
        hs, WK_A_w, nullptr, gtmp, MTOT, RR, DD);
    hmma_gemm<true><<<dim3(DD / 128, MTOT / 128), blk, HMMA_SMEM>>>(
        gtmp, WK_B_w, WK_B_b, gk, MTOT, DD, RR);
    // tmp = hs @ WV_A^T ; V = tmp @ WV_B^T + b
    hmma_gemm<false><<<dim3(RR / 128, MTOT / 128), blk, HMMA_SMEM>>>(
        hs, WV_A_w, nullptr, gtmp, MTOT, RR, DD);
    hmma_gemm<true><<<dim3(DD / 128, MTOT / 128), blk, HMMA_SMEM>>>(
        gtmp, WV_B_w, WV_B_b, gv, MTOT, DD, RR);

    // causal attention (fp32 SIMT)
    attn_kernel<<<dim3(SS / 64, HH, BB), blk, smem_attn>>>(gq, gk, gv, gatt);

    // out = att @ c_proj + b   (via transposed weights)
    hmma_gemm<true><<<dim3(DD / 128, MTOT / 128), blk, HMMA_SMEM>>>(
        gatt, gcpt, c_b, out, MTOT, DD, DD);

    (void)in_sizes; (void)n_in; (void)out_size;
}

// round 5
// speedup vs baseline: 2.8464x; 1.8340x over previous
#include <cuda_runtime.h>
#include <cuda_bf16.h>
#include <cstdint>
#include <cstddef>

// Problem dims (fixed)
#define BB 4
#define SS 2048
#define DD 1024
#define HH 16
#define HD 64
#define RR 512
#define MTOT (BB*SS)          // 8192 rows

// ---------------- scratch (device globals: allocation-guard safe) -------------
__device__ float g_q  [(size_t)MTOT * DD];   // 32 MB
__device__ float g_k  [(size_t)MTOT * DD];   // 32 MB
__device__ float g_v  [(size_t)MTOT * DD];   // 32 MB
__device__ float g_att[(size_t)MTOT * DD];   // 32 MB
__device__ float g_tmp[(size_t)MTOT * RR];   // 16 MB
__device__ float g_cpt[(size_t)DD * DD];     // 4 MB  (c_proj transposed -> [N,K])

// ---------------- mma.sync helpers (family-stable, OK on compute_103) ----------
__device__ __forceinline__ uint32_t smem_u32(const void* p) {
    uint32_t a;
    asm("{ .reg .u64 t; cvta.to.shared.u64 t, %1; cvt.u32.u64 %0, t; }"
        : "=r"(a) : "l"(p));
    return a;
}

__device__ __forceinline__ void ldsm_x4(uint32_t addr, uint32_t* r) {
    asm volatile("ldmatrix.sync.aligned.m8n8.x4.shared.b16 {%0,%1,%2,%3}, [%4];"
                 : "=r"(r[0]), "=r"(r[1]), "=r"(r[2]), "=r"(r[3]) : "r"(addr));
}
__device__ __forceinline__ void ldsm_x4_t(uint32_t addr, uint32_t* r) {
    asm volatile("ldmatrix.sync.aligned.m8n8.x4.trans.shared.b16 {%0,%1,%2,%3}, [%4];"
                 : "=r"(r[0]), "=r"(r[1]), "=r"(r[2]), "=r"(r[3]) : "r"(addr));
}
__device__ __forceinline__ void mma16816(float* d, const uint32_t* a, const uint32_t* b) {
    asm volatile(
        "mma.sync.aligned.m16n8k16.row.col.f32.bf16.bf16.f32 "
        "{%0,%1,%2,%3}, {%4,%5,%6,%7}, {%8,%9}, {%0,%1,%2,%3};"
        : "+f"(d[0]), "+f"(d[1]), "+f"(d[2]), "+f"(d[3])
        : "r"(a[0]), "r"(a[1]), "r"(a[2]), "r"(a[3]), "r"(b[0]), "r"(b[1]));
}

// split a float4 into packed-bf16 hi(8B) and lo(8B)
__device__ __forceinline__ void split_f4(float4 v, uint2& hi, uint2& lo) {
    __nv_bfloat16 h0 = __float2bfloat16(v.x), h1 = __float2bfloat16(v.y);
    __nv_bfloat16 h2 = __float2bfloat16(v.z), h3 = __float2bfloat16(v.w);
    __nv_bfloat16 l0 = __float2bfloat16(v.x - __bfloat162float(h0));
    __nv_bfloat16 l1 = __float2bfloat16(v.y - __bfloat162float(h1));
    __nv_bfloat16 l2 = __float2bfloat16(v.z - __bfloat162float(h2));
    __nv_bfloat16 l3 = __float2bfloat16(v.w - __bfloat162float(h3));
    __nv_bfloat162 hp0(h0, h1), hp1(h2, h3), lp0(l0, l1), lp1(l2, l3);
    hi.x = *reinterpret_cast<uint32_t*>(&hp0);
    hi.y = *reinterpret_cast<uint32_t*>(&hp1);
    lo.x = *reinterpret_cast<uint32_t*>(&lp0);
    lo.y = *reinterpret_cast<uint32_t*>(&lp1);
}

// split a pair of floats into packed bf16 hi / lo
__device__ __forceinline__ void split2(float x, float y, uint32_t& hi, uint32_t& lo) {
    __nv_bfloat16 hx = __float2bfloat16(x), hy = __float2bfloat16(y);
    __nv_bfloat16 lx = __float2bfloat16(x - __bfloat162float(hx));
    __nv_bfloat16 ly = __float2bfloat16(y - __bfloat162float(hy));
    __nv_bfloat162 hp(hx, hy), lp(lx, ly);
    hi = *reinterpret_cast<uint32_t*>(&hp);
    lo = *reinterpret_cast<uint32_t*>(&lp);
}

// ---------------- HMMA bf16x3 GEMM (unchanged, verified R4) --------------------
#define PITCH 80
#define TILE_B (128 * PITCH)
#define STAGE_B (4 * TILE_B)
#define HMMA_SMEM (2 * STAGE_B)

template <bool BIAS>
__global__ void __launch_bounds__(256)
hmma_gemm(const float* __restrict__ A, const float* __restrict__ B,
          const float* __restrict__ bias, float* __restrict__ C,
          int M, int N, int K)
{
    extern __shared__ char smem[];
    const uint32_t sb = smem_u32(smem);

    const int tid  = threadIdx.x;
    const int lane = tid & 31;
    const int wid  = tid >> 5;
    const int m0 = blockIdx.y * 128, n0 = blockIdx.x * 128;
    const int wm = (wid & 3) * 32;
    const int wn = (wid >> 2) * 64;

    const int lr = tid >> 3;
    const int lq = tid & 7;

    const int a_row = wm + (lane & 7) + ((lane >> 3) & 1) * 8;
    const int a_kb  = ((lane >> 4) & 1) * 16;
    const int b_row = wn + (lane & 7) + ((lane >> 4) & 1) * 8;
    const int b_kb  = ((lane >> 3) & 1) * 16;

    float acc[2][8][4];
#pragma unroll
    for (int i = 0; i < 2; i++)
#pragma unroll
        for (int j = 0; j < 8; j++)
#pragma unroll
            for (int k = 0; k < 4; k++) acc[i][j][k] = 0.f;

    const int NC = K >> 5;

    float4 ra[4], rb[4];
#pragma unroll
    for (int p = 0; p < 4; p++) {
        int row = lr + p * 32;
        ra[p] = *reinterpret_cast<const float4*>(&A[(size_t)(m0 + row) * K + lq * 4]);
        rb[p] = *reinterpret_cast<const float4*>(&B[(size_t)(n0 + row) * K + lq * 4]);
    }
#pragma unroll
    for (int p = 0; p < 4; p++) {
        int row = lr + p * 32;
        uint32_t off = (uint32_t)(row * PITCH + lq * 8);
        uint2 hi, lo;
        split_f4(ra[p], hi, lo);
        *reinterpret_cast<uint2*>(smem + (off))              = hi;
        *reinterpret_cast<uint2*>(smem + (off + TILE_B))     = lo;
        split_f4(rb[p], hi, lo);
        *reinterpret_cast<uint2*>(smem + (off + 2 * TILE_B)) = hi;
        *reinterpret_cast<uint2*>(smem + (off + 3 * TILE_B)) = lo;
    }
    __syncthreads();

    for (int c = 0; c < NC; c++) {
        if (c + 1 < NC) {
            const int kc = (c + 1) << 5;
#pragma unroll
            for (int p = 0; p < 4; p++) {
                int row = lr + p * 32;
                ra[p] = *reinterpret_cast<const float4*>(
                    &A[(size_t)(m0 + row) * K + kc + lq * 4]);
                rb[p] = *reinterpret_cast<const float4*>(
                    &B[(size_t)(n0 + row) * K + kc + lq * 4]);
            }
        }

        const uint32_t st = sb + (uint32_t)(c & 1) * STAGE_B;
#pragma unroll
        for (int ks = 0; ks < 2; ks++) {
            uint32_t ah[2][4], al[2][4];
#pragma unroll
            for (int mt = 0; mt < 2; mt++) {
                uint32_t aaddr = st + (uint32_t)((a_row + mt * 16) * PITCH + a_kb + ks * 32);
                ldsm_x4(aaddr, ah[mt]);
                ldsm_x4(aaddr + TILE_B, al[mt]);
            }
#pragma unroll
            for (int nt2 = 0; nt2 < 4; nt2++) {
                uint32_t bh[4], bl[4];
                uint32_t baddr = st + 2 * TILE_B +
                    (uint32_t)((b_row + nt2 * 16) * PITCH + b_kb + ks * 32);
                ldsm_x4(baddr, bh);
                ldsm_x4(baddr + TILE_B, bl);
#pragma unroll
                for (int mt = 0; mt < 2; mt++) {
#pragma unroll
                    for (int half = 0; half < 2; half++) {
                        float* d = acc[mt][nt2 * 2 + half];
                        mma16816(d, ah[mt], &bh[half * 2]);
                        mma16816(d, ah[mt], &bl[half * 2]);
                        mma16816(d, al[mt], &bh[half * 2]);
                    }
                }
            }
        }

        if (c + 1 < NC) {
            char* so = smem + (size_t)((c + 1) & 1) * STAGE_B;
#pragma unroll
            for (int p = 0; p < 4; p++) {
                int row = lr + p * 32;
                uint32_t off = (uint32_t)(row * PITCH + lq * 8);
                uint2 hi, lo;
                split_f4(ra[p], hi, lo);
                *reinterpret_cast<uint2*>(so + off)              = hi;
                *reinterpret_cast<uint2*>(so + off + TILE_B)     = lo;
                split_f4(rb[p], hi, lo);
                *reinterpret_cast<uint2*>(so + off + 2 * TILE_B) = hi;
                *reinterpret_cast<uint2*>(so + off + 3 * TILE_B) = lo;
            }
        }
        __syncthreads();
    }

    const int g = lane >> 2;
    const int cpair = (lane & 3) * 2;
#pragma unroll
    for (int mt = 0; mt < 2; mt++) {
#pragma unroll
        for (int nt = 0; nt < 8; nt++) {
            int col = n0 + wn + nt * 8 + cpair;
            float bx = 0.f, by = 0.f;
            if (BIAS) { bx = bias[col]; by = bias[col + 1]; }
            int row0 = m0 + wm + mt * 16 + g;
            float2 v0 = make_float2(acc[mt][nt][0] + bx, acc[mt][nt][1] + by);
            float2 v1 = make_float2(acc[mt][nt][2] + bx, acc[mt][nt][3] + by);
            *reinterpret_cast<float2*>(&C[(size_t)row0 * N + col])       = v0;
            *reinterpret_cast<float2*>(&C[(size_t)(row0 + 8) * N + col]) = v1;
        }
    }
}

// ---------------- fp32 transpose (for c_proj: [K,N] -> [N,K]) ------------------
__global__ void __launch_bounds__(256)
transpose_kernel(const float* __restrict__ W, float* __restrict__ out, int K, int N)
{
    __shared__ float t[32][33];
    int k0 = blockIdx.y * 32, n0 = blockIdx.x * 32;
    int tx = threadIdx.x & 31, ty = threadIdx.x >> 5;
#pragma unroll
    for (int i = 0; i < 32; i += 8)
        t[ty + i][tx] = W[(size_t)(k0 + ty + i) * N + n0 + tx];
    __syncthreads();
#pragma unroll
    for (int i = 0; i < 32; i += 8)
        out[(size_t)(n0 + ty + i) * K + k0 + tx] = t[tx][ty + i];
}

// ---------------- HMMA flash attention (bf16x3) ---------------------------------
// grid (S/128, H, B), 256 threads (8 warps x 16 q-rows), k-tiles of 64.
#define APITCH 144                 // bytes per 64-bf16 row (128B + 16B pad)
#define QTILE (128 * APITCH)       // 18432
#define KTILE (64 * APITCH)        // 9216
#define ATT_SMEM (2 * QTILE + 4 * KTILE)   // 73728

__global__ void __launch_bounds__(256)
attn_mma_kernel(const float* __restrict__ Q, const float* __restrict__ Kg,
                const float* __restrict__ Vg, float* __restrict__ O)
{
    extern __shared__ char smem[];
    const uint32_t sb = smem_u32(smem);
    const int tid = threadIdx.x, lane = tid & 31, wid = tid >> 5;
    const int qt = blockIdx.x, h = blockIdx.y, b = blockIdx.z;
    const int q0 = qt * 128;
    const int wm = wid * 16;

    // --- load Q tile (128 x 64) split hi/lo ---
    const float* qbase = Q + ((size_t)b * SS + q0) * DD + h * HD;
#pragma unroll
    for (int it = 0; it < 8; it++) {
        int idx = tid + it * 256;        // 0..2047
        int row = idx >> 4, c4 = idx & 15;
        float4 v = *reinterpret_cast<const float4*>(&qbase[(size_t)row * DD + c4 * 4]);
        uint2 hi, lo;
        split_f4(v, hi, lo);
        uint32_t off = (uint32_t)(row * APITCH + c4 * 8);
        *reinterpret_cast<uint2*>(smem + off)         = hi;
        *reinterpret_cast<uint2*>(smem + off + QTILE) = lo;
    }

    // fragment address components
    const int g  = lane >> 2;
    const int qd = lane & 3;
    const uint32_t a_off = (uint32_t)((wm + (lane & 7) + ((lane >> 3) & 1) * 8) * APITCH
                                      + ((lane >> 4) & 1) * 16);
    const uint32_t b_off = (uint32_t)(((lane & 7) + ((lane >> 4) & 1) * 8) * APITCH
                                      + ((lane >> 3) & 1) * 16);
    const uint32_t v_off = (uint32_t)(((lane & 7) + ((lane >> 3) & 1) * 8) * APITCH
                                      + ((lane >> 4) & 1) * 16);

    float m0 = -1e30f, m1 = -1e30f, l0 = 0.f, l1 = 0.f;
    float o[8][4];
#pragma unroll
    for (int i = 0; i < 8; i++)
#pragma unroll
        for (int j = 0; j < 4; j++) o[i][j] = 0.f;

    const int row0 = q0 + wm + g;
    const int nkt = 2 * qt + 2;

    for (int kt = 0; kt < nkt; kt++) {
        __syncthreads();
        // --- load K,V tiles (64 x 64 each) split hi/lo ---
        const float* kbase = Kg + ((size_t)b * SS + kt * 64) * DD + h * HD;
        const float* vbase = Vg + ((size_t)b * SS + kt * 64) * DD + h * HD;
#pragma unroll
        for (int it = 0; it < 4; it++) {
            int idx = tid + it * 256;    // 0..1023
            int row = idx >> 4, c4 = idx & 15;
            uint32_t off = (uint32_t)(row * APITCH + c4 * 8);
            float4 v = *reinterpret_cast<const float4*>(&kbase[(size_t)row * DD + c4 * 4]);
            uint2 hi, lo;
            split_f4(v, hi, lo);
            *reinterpret_cast<uint2*>(smem + 2 * QTILE + off)         = hi;
            *reinterpret_cast<uint2*>(smem + 2 * QTILE + KTILE + off) = lo;
            v = *reinterpret_cast<const float4*>(&vbase[(size_t)row * DD + c4 * 4]);
            split_f4(v, hi, lo);
            *reinterpret_cast<uint2*>(smem + 2 * QTILE + 2 * KTILE + off) = hi;
            *reinterpret_cast<uint2*>(smem + 2 * QTILE + 3 * KTILE + off) = lo;
        }
        __syncthreads();

        // warps entirely above this k-tile have nothing to do
        if (kt * 64 > q0 + wm + 15) continue;

        // --- S = Q K^T (bf16x3) ---
        float s[8][4];
#pragma unroll
        for (int i = 0; i < 8; i++)
#pragma unroll
            for (int j = 0; j < 4; j++) s[i][j] = 0.f;

#pragma unroll
        for (int ks = 0; ks < 4; ks++) {
            uint32_t qh[4], ql[4];
            uint32_t qa = sb + a_off + ks * 32;
            ldsm_x4(qa, qh);
            ldsm_x4(qa + QTILE, ql);
#pragma unroll
            for (int np = 0; np < 4; np++) {
                uint32_t kh[4], kl[4];
                uint32_t ka = sb + 2 * QTILE + b_off + np * 16 * APITCH + ks * 32;
                ldsm_x4(ka, kh);
                ldsm_x4(ka + KTILE, kl);
#pragma unroll
                for (int hh = 0; hh < 2; hh++) {
                    float* d = s[np * 2 + hh];
                    mma16816(d, qh, &kh[hh * 2]);
                    mma16816(d, qh, &kl[hh * 2]);
                    mma16816(d, ql, &kh[hh * 2]);
                }
            }
        }

        // --- scale + causal mask ---
        const int kbase0 = kt * 64;
        if (kbase0 + 63 > row0) {
#pragma unroll
            for (int nt = 0; nt < 8; nt++) {
                int col = kbase0 + nt * 8 + qd * 2;
                s[nt][0] = (col     <= row0)     ? s[nt][0] * 0.125f : -1e30f;
                s[nt][1] = (col + 1 <= row0)     ? s[nt][1] * 0.125f : -1e30f;
                s[nt][2] = (col     <= row0 + 8) ? s[nt][2] * 0.125f : -1e30f;
                s[nt][3] = (col + 1 <= row0 + 8) ? s[nt][3] * 0.125f : -1e30f;
            }
        } else {
#pragma unroll
            for (int nt = 0; nt < 8; nt++) {
                s[nt][0] *= 0.125f; s[nt][1] *= 0.125f;
                s[nt][2] *= 0.125f; s[nt][3] *= 0.125f;
            }
        }

        // --- online softmax (rows g and g+8) ---
        float mx0 = -1e30f, mx1 = -1e30f;
#pragma unroll
        for (int nt = 0; nt < 8; nt++) {
            mx0 = fmaxf(mx0, fmaxf(s[nt][0], s[nt][1]));
            mx1 = fmaxf(mx1, fmaxf(s[nt][2], s[nt][3]));
        }
        mx0 = fmaxf(mx0, __shfl_xor_sync(0xffffffffu, mx0, 1));
        mx0 = fmaxf(mx0, __shfl_xor_sync(0xffffffffu, mx0, 2));
        mx1 = fmaxf(mx1, __shfl_xor_sync(0xffffffffu, mx1, 1));
        mx1 = fmaxf(mx1, __shfl_xor_sync(0xffffffffu, mx1, 2));

        float mn0 = fmaxf(m0, mx0), mn1 = fmaxf(m1, mx1);
        float c0 = __expf(m0 - mn0), c1 = __expf(m1 - mn1);
        m0 = mn0; m1 = mn1;

        float sum0 = 0.f, sum1 = 0.f;
#pragma unroll
        for (int nt = 0; nt < 8; nt++) {
            s[nt][0] = __expf(s[nt][0] - mn0); sum0 += s[nt][0];
            s[nt][1] = __expf(s[nt][1] - mn0); sum0 += s[nt][1];
            s[nt][2] = __expf(s[nt][2] - mn1); sum1 += s[nt][2];
            s[nt][3] = __expf(s[nt][3] - mn1); sum1 += s[nt][3];
        }
        sum0 += __shfl_xor_sync(0xffffffffu, sum0, 1);
        sum0 += __shfl_xor_sync(0xffffffffu, sum0, 2);
        sum1 += __shfl_xor_sync(0xffffffffu, sum1, 1);
        sum1 += __shfl_xor_sync(0xffffffffu, sum1, 2);
        l0 = l0 * c0 + sum0;
        l1 = l1 * c1 + sum1;

#pragma unroll
        for (int nt = 0; nt < 8; nt++) {
            o[nt][0] *= c0; o[nt][1] *= c0;
            o[nt][2] *= c1; o[nt][3] *= c1;
        }

        // --- O += P V (bf16x3; P fragment reuses S accumulator layout) ---
#pragma unroll
        for (int kc = 0; kc < 4; kc++) {
            uint32_t ph[4], pl[4];
            split2(s[2 * kc][0],     s[2 * kc][1],     ph[0], pl[0]);
            split2(s[2 * kc][2],     s[2 * kc][3],     ph[1], pl[1]);
            split2(s[2 * kc + 1][0], s[2 * kc + 1][1], ph[2], pl[2]);
            split2(s[2 * kc + 1][2], s[2 * kc + 1][3], ph[3], pl[3]);
#pragma unroll
            for (int np = 0; np < 4; np++) {
                uint32_t vh[4], vl[4];
                uint32_t va = sb + 2 * QTILE + 2 * KTILE + v_off
                              + kc * 16 * APITCH + np * 32;
                ldsm_x4_t(va, vh);
                ldsm_x4_t(va + KTILE, vl);
#pragma unroll
                for (int hh = 0; hh < 2; hh++) {
                    float* d = o[np * 2 + hh];
                    mma16816(d, ph, &vh[hh * 2]);
                    mma16816(d, ph, &vl[hh * 2]);
                    mma16816(d, pl, &vh[hh * 2]);
                }
            }
        }
    }

    // --- epilogue: normalize and store ---
    const float inv0 = 1.0f / l0, inv1 = 1.0f / l1;
    float* ob0 = O + ((size_t)b * SS + row0) * DD + h * HD;
    float* ob1 = O + ((size_t)b * SS + row0 + 8) * DD + h * HD;
#pragma unroll
    for (int nt = 0; nt < 8; nt++) {
        int col = nt * 8 + qd * 2;
        *reinterpret_cast<float2*>(&ob0[col]) =
            make_float2(o[nt][0] * inv0, o[nt][1] * inv0);
        *reinterpret_cast<float2*>(&ob1[col]) =
            make_float2(o[nt][2] * inv1, o[nt][3] * inv1);
    }
}

// ---------------- launch ------------------------------------------------------
extern "C" void kernel_launch(void* const* d_in, const int* in_sizes, int n_in,
                              void* d_out, int out_size)
{
    const float* hs     = (const float*)d_in[0];
    const float* WQ_w   = (const float*)d_in[1];
    const float* WQ_b   = (const float*)d_in[2];
    const float* WK_A_w = (const float*)d_in[3];
    const float* WK_B_w = (const float*)d_in[4];
    const float* WK_B_b = (const float*)d_in[5];
    const float* WV_A_w = (const float*)d_in[6];
    const float* WV_B_w = (const float*)d_in[7];
    const float* WV_B_b = (const float*)d_in[8];
    const float* c_w    = (const float*)d_in[9];
    const float* c_b    = (const float*)d_in[10];
    float* out = (float*)d_out;

    float *gq, *gk, *gv, *gatt, *gtmp, *gcpt;
    cudaGetSymbolAddress((void**)&gq,   g_q);
    cudaGetSymbolAddress((void**)&gk,   g_k);
    cudaGetSymbolAddress((void**)&gv,   g_v);
    cudaGetSymbolAddress((void**)&gatt, g_att);
    cudaGetSymbolAddress((void**)&gtmp, g_tmp);
    cudaGetSymbolAddress((void**)&gcpt, g_cpt);

    cudaFuncSetAttribute(hmma_gemm<true>,
                         cudaFuncAttributeMaxDynamicSharedMemorySize, HMMA_SMEM);
    cudaFuncSetAttribute(hmma_gemm<false>,
                         cudaFuncAttributeMaxDynamicSharedMemorySize, HMMA_SMEM);
    cudaFuncSetAttribute(attn_mma_kernel,
                         cudaFuncAttributeMaxDynamicSharedMemorySize, ATT_SMEM);

    dim3 blk(256);

    // c_proj: [K,N] -> [N,K] once
    transpose_kernel<<<dim3(DD / 32, DD / 32), blk>>>(c_w, gcpt, DD, DD);

    // Q = hs @ WQ^T + b
    hmma_gemm<true><<<dim3(DD / 128, MTOT / 128), blk, HMMA_SMEM>>>(
        hs, WQ_w, WQ_b, gq, MTOT, DD, DD);
    // tmp = hs @ WK_A^T ; K = tmp @ WK_B^T + b
    hmma_gemm<false><<<dim3(RR / 128, MTOT / 128), blk, HMMA_SMEM>>>(
        hs, WK_A_w, nullptr, gtmp, MTOT, RR, DD);
    hmma_gemm<true><<<dim3(DD / 128, MTOT / 128), blk, HMMA_SMEM>>>(
        gtmp, WK_B_w, WK_B_b, gk, MTOT, DD, RR);
    // tmp = hs @ WV_A^T ; V = tmp @ WV_B^T + b
    hmma_gemm<false><<<dim3(RR / 128, MTOT / 128), blk, HMMA_SMEM>>>(
        hs, WV_A_w, nullptr, gtmp, MTOT, RR, DD);
    hmma_gemm<true><<<dim3(DD / 128, MTOT / 128), blk, HMMA_SMEM>>>(
        gtmp, WV_B_w, WV_B_b, gv, MTOT, DD, RR);

    // causal attention (HMMA flash)
    attn_mma_kernel<<<dim3(SS / 128, HH, BB), blk, ATT_SMEM>>>(gq, gk, gv, gatt);

    // out = att @ c_proj + b   (via transposed weights)
    hmma_gemm<true><<<dim3(DD / 128, MTOT / 128), blk, HMMA_SMEM>>>(
        gatt, gcpt, c_b, out, MTOT, DD, DD);

    (void)in_sizes; (void)n_in; (void)out_size;
}

// round 6
// speedup vs baseline: 2.9723x; 1.0442x over previous
#include <cuda_runtime.h>
#include <cuda_bf16.h>
#include <cstdint>
#include <cstddef>

// Problem dims (fixed)
#define BB 4
#define SS 2048
#define DD 1024
#define HH 16
#define HD 64
#define RR 512
#define MTOT (BB*SS)          // 8192 rows

// ---------------- scratch (device globals: allocation-guard safe) -------------
__device__ float g_att[(size_t)MTOT * DD];   // 32 MB
__device__ float g_tmp[(size_t)MTOT * RR];   // 16 MB
__device__ float g_cpt[(size_t)DD * DD];     // 4 MB  (c_proj transposed -> [N,K])
// split bf16 Q/K/V (written by projection GEMM epilogues)
__device__ __nv_bfloat16 g_qhi[(size_t)MTOT * DD];
__device__ __nv_bfloat16 g_qlo[(size_t)MTOT * DD];
__device__ __nv_bfloat16 g_khi[(size_t)MTOT * DD];
__device__ __nv_bfloat16 g_klo[(size_t)MTOT * DD];
__device__ __nv_bfloat16 g_vhi[(size_t)MTOT * DD];
__device__ __nv_bfloat16 g_vlo[(size_t)MTOT * DD];

// ---------------- mma.sync helpers (family-stable, OK on compute_103) ----------
__device__ __forceinline__ uint32_t smem_u32(const void* p) {
    uint32_t a;
    asm("{ .reg .u64 t; cvta.to.shared.u64 t, %1; cvt.u32.u64 %0, t; }"
        : "=r"(a) : "l"(p));
    return a;
}

__device__ __forceinline__ void ldsm_x4(uint32_t addr, uint32_t* r) {
    asm volatile("ldmatrix.sync.aligned.m8n8.x4.shared.b16 {%0,%1,%2,%3}, [%4];"
                 : "=r"(r[0]), "=r"(r[1]), "=r"(r[2]), "=r"(r[3]) : "r"(addr));
}
__device__ __forceinline__ void ldsm_x4_t(uint32_t addr, uint32_t* r) {
    asm volatile("ldmatrix.sync.aligned.m8n8.x4.trans.shared.b16 {%0,%1,%2,%3}, [%4];"
                 : "=r"(r[0]), "=r"(r[1]), "=r"(r[2]), "=r"(r[3]) : "r"(addr));
}
__device__ __forceinline__ void mma16816(float* d, const uint32_t* a, const uint32_t* b) {
    asm volatile(
        "mma.sync.aligned.m16n8k16.row.col.f32.bf16.bf16.f32 "
        "{%0,%1,%2,%3}, {%4,%5,%6,%7}, {%8,%9}, {%0,%1,%2,%3};"
        : "+f"(d[0]), "+f"(d[1]), "+f"(d[2]), "+f"(d[3])
        : "r"(a[0]), "r"(a[1]), "r"(a[2]), "r"(a[3]), "r"(b[0]), "r"(b[1]));
}

__device__ __forceinline__ void cp16(uint32_t dst, const void* src) {
    asm volatile("cp.async.cg.shared.global [%0], [%1], 16;"
                 :: "r"(dst), "l"(src) : "memory");
}
#define CP_COMMIT()  asm volatile("cp.async.commit_group;" ::: "memory")
#define CP_WAIT1()   asm volatile("cp.async.wait_group 1;" ::: "memory")
#define CP_WAIT0()   asm volatile("cp.async.wait_group 0;" ::: "memory")

// split a float4 into packed-bf16 hi(8B) and lo(8B)
__device__ __forceinline__ void split_f4(float4 v, uint2& hi, uint2& lo) {
    __nv_bfloat16 h0 = __float2bfloat16(v.x), h1 = __float2bfloat16(v.y);
    __nv_bfloat16 h2 = __float2bfloat16(v.z), h3 = __float2bfloat16(v.w);
    __nv_bfloat16 l0 = __float2bfloat16(v.x - __bfloat162float(h0));
    __nv_bfloat16 l1 = __float2bfloat16(v.y - __bfloat162float(h1));
    __nv_bfloat16 l2 = __float2bfloat16(v.z - __bfloat162float(h2));
    __nv_bfloat16 l3 = __float2bfloat16(v.w - __bfloat162float(h3));
    __nv_bfloat162 hp0(h0, h1), hp1(h2, h3), lp0(l0, l1), lp1(l2, l3);
    hi.x = *reinterpret_cast<uint32_t*>(&hp0);
    hi.y = *reinterpret_cast<uint32_t*>(&hp1);
    lo.x = *reinterpret_cast<uint32_t*>(&lp0);
    lo.y = *reinterpret_cast<uint32_t*>(&lp1);
}

// split a pair of floats into packed bf16 hi / lo
__device__ __forceinline__ void split2(float x, float y, uint32_t& hi, uint32_t& lo) {
    __nv_bfloat16 hx = __float2bfloat16(x), hy = __float2bfloat16(y);
    __nv_bfloat16 lx = __float2bfloat16(x - __bfloat162float(hx));
    __nv_bfloat16 ly = __float2bfloat16(y - __bfloat162float(hy));
    __nv_bfloat162 hp(hx, hy), lp(lx, ly);
    hi = *reinterpret_cast<uint32_t*>(&hp);
    lo = *reinterpret_cast<uint32_t*>(&lp);
}

// ---------------- HMMA bf16x3 GEMM ---------------------------------------------
// C[M,N] = A[M,K] @ B[N,K]^T (+ bias). fp32 in; out fp32 (C) or split bf16 hi/lo.
#define PITCH 80
#define TILE_B (128 * PITCH)
#define STAGE_B (4 * TILE_B)
#define HMMA_SMEM (2 * STAGE_B)

template <bool BIAS, bool SPLITOUT>
__global__ void __launch_bounds__(256)
hmma_gemm(const float* __restrict__ A, const float* __restrict__ B,
          const float* __restrict__ bias, float* __restrict__ C,
          __nv_bfloat16* __restrict__ Chi, __nv_bfloat16* __restrict__ Clo,
          int M, int N, int K)
{
    extern __shared__ char smem[];
    const uint32_t sb = smem_u32(smem);

    const int tid  = threadIdx.x;
    const int lane = tid & 31;
    const int wid  = tid >> 5;
    const int m0 = blockIdx.y * 128, n0 = blockIdx.x * 128;
    const int wm = (wid & 3) * 32;
    const int wn = (wid >> 2) * 64;

    const int lr = tid >> 3;
    const int lq = tid & 7;

    const int a_row = wm + (lane & 7) + ((lane >> 3) & 1) * 8;
    const int a_kb  = ((lane >> 4) & 1) * 16;
    const int b_row = wn + (lane & 7) + ((lane >> 4) & 1) * 8;
    const int b_kb  = ((lane >> 3) & 1) * 16;

    float acc[2][8][4];
#pragma unroll
    for (int i = 0; i < 2; i++)
#pragma unroll
        for (int j = 0; j < 8; j++)
#pragma unroll
            for (int k = 0; k < 4; k++) acc[i][j][k] = 0.f;

    const int NC = K >> 5;

    float4 ra[4], rb[4];
#pragma unroll
    for (int p = 0; p < 4; p++) {
        int row = lr + p * 32;
        ra[p] = *reinterpret_cast<const float4*>(&A[(size_t)(m0 + row) * K + lq * 4]);
        rb[p] = *reinterpret_cast<const float4*>(&B[(size_t)(n0 + row) * K + lq * 4]);
    }
#pragma unroll
    for (int p = 0; p < 4; p++) {
        int row = lr + p * 32;
        uint32_t off = (uint32_t)(row * PITCH + lq * 8);
        uint2 hi, lo;
        split_f4(ra[p], hi, lo);
        *reinterpret_cast<uint2*>(smem + (off))              = hi;
        *reinterpret_cast<uint2*>(smem + (off + TILE_B))     = lo;
        split_f4(rb[p], hi, lo);
        *reinterpret_cast<uint2*>(smem + (off + 2 * TILE_B)) = hi;
        *reinterpret_cast<uint2*>(smem + (off + 3 * TILE_B)) = lo;
    }
    __syncthreads();

    for (int c = 0; c < NC; c++) {
        if (c + 1 < NC) {
            const int kc = (c + 1) << 5;
#pragma unroll
            for (int p = 0; p < 4; p++) {
                int row = lr + p * 32;
                ra[p] = *reinterpret_cast<const float4*>(
                    &A[(size_t)(m0 + row) * K + kc + lq * 4]);
                rb[p] = *reinterpret_cast<const float4*>(
                    &B[(size_t)(n0 + row) * K + kc + lq * 4]);
            }
        }

        const uint32_t st = sb + (uint32_t)(c & 1) * STAGE_B;
#pragma unroll
        for (int ks = 0; ks < 2; ks++) {
            uint32_t ah[2][4], al[2][4];
#pragma unroll
            for (int mt = 0; mt < 2; mt++) {
                uint32_t aaddr = st + (uint32_t)((a_row + mt * 16) * PITCH + a_kb + ks * 32);
                ldsm_x4(aaddr, ah[mt]);
                ldsm_x4(aaddr + TILE_B, al[mt]);
            }
#pragma unroll
            for (int nt2 = 0; nt2 < 4; nt2++) {
                uint32_t bh[4], bl[4];
                uint32_t baddr = st + 2 * TILE_B +
                    (uint32_t)((b_row + nt2 * 16) * PITCH + b_kb + ks * 32);
                ldsm_x4(baddr, bh);
                ldsm_x4(baddr + TILE_B, bl);
#pragma unroll
                for (int mt = 0; mt < 2; mt++) {
#pragma unroll
                    for (int half = 0; half < 2; half++) {
                        float* d = acc[mt][nt2 * 2 + half];
                        mma16816(d, ah[mt], &bh[half * 2]);
                        mma16816(d, ah[mt], &bl[half * 2]);
                        mma16816(d, al[mt], &bh[half * 2]);
                    }
                }
            }
        }

        if (c + 1 < NC) {
            char* so = smem + (size_t)((c + 1) & 1) * STAGE_B;
#pragma unroll
            for (int p = 0; p < 4; p++) {
                int row = lr + p * 32;
                uint32_t off = (uint32_t)(row * PITCH + lq * 8);
                uint2 hi, lo;
                split_f4(ra[p], hi, lo);
                *reinterpret_cast<uint2*>(so + off)              = hi;
                *reinterpret_cast<uint2*>(so + off + TILE_B)     = lo;
                split_f4(rb[p], hi, lo);
                *reinterpret_cast<uint2*>(so + off + 2 * TILE_B) = hi;
                *reinterpret_cast<uint2*>(so + off + 3 * TILE_B) = lo;
            }
        }
        __syncthreads();
    }

    const int g = lane >> 2;
    const int cpair = (lane & 3) * 2;
#pragma unroll
    for (int mt = 0; mt < 2; mt++) {
#pragma unroll
        for (int nt = 0; nt < 8; nt++) {
            int col = n0 + wn + nt * 8 + cpair;
            float bx = 0.f, by = 0.f;
            if (BIAS) { bx = bias[col]; by = bias[col + 1]; }
            int row0 = m0 + wm + mt * 16 + g;
            float x0 = acc[mt][nt][0] + bx, y0 = acc[mt][nt][1] + by;
            float x1 = acc[mt][nt][2] + bx, y1 = acc[mt][nt][3] + by;
            if (SPLITOUT) {
                uint32_t hi, lo;
                size_t o0 = (size_t)row0 * N + col;
                size_t o1 = (size_t)(row0 + 8) * N + col;
                split2(x0, y0, hi, lo);
                *reinterpret_cast<uint32_t*>(Chi + o0) = hi;
                *reinterpret_cast<uint32_t*>(Clo + o0) = lo;
                split2(x1, y1, hi, lo);
                *reinterpret_cast<uint32_t*>(Chi + o1) = hi;
                *reinterpret_cast<uint32_t*>(Clo + o1) = lo;
            } else {
                *reinterpret_cast<float2*>(&C[(size_t)row0 * N + col]) =
                    make_float2(x0, y0);
                *reinterpret_cast<float2*>(&C[(size_t)(row0 + 8) * N + col]) =
                    make_float2(x1, y1);
            }
        }
    }
}

// ---------------- fp32 transpose (for c_proj: [K,N] -> [N,K]) ------------------
__global__ void __launch_bounds__(256)
transpose_kernel(const float* __restrict__ W, float* __restrict__ out, int K, int N)
{
    __shared__ float t[32][33];
    int k0 = blockIdx.y * 32, n0 = blockIdx.x * 32;
    int tx = threadIdx.x & 31, ty = threadIdx.x >> 5;
#pragma unroll
    for (int i = 0; i < 32; i += 8)
        t[ty + i][tx] = W[(size_t)(k0 + ty + i) * N + n0 + tx];
    __syncthreads();
#pragma unroll
    for (int i = 0; i < 32; i += 8)
        out[(size_t)(n0 + ty + i) * K + k0 + tx] = t[tx][ty + i];
}

// ---------------- HMMA flash attention (bf16 pre-split, cp.async pipelined) ----
// grid (S/128, H, B), 256 threads (8 warps x 16 q-rows), k-tiles of 64, 2 stages.
#define APITCH 144                 // bytes per 64-bf16 row (128B + 16B pad)
#define QTILE (128 * APITCH)       // 18432
#define KTILE (64 * APITCH)        // 9216
#define STAGEA (4 * KTILE)         // Khi,Klo,Vhi,Vlo = 36864
#define ATT_SMEM (2 * QTILE + 2 * STAGEA)   // 110592

__global__ void __launch_bounds__(256)
attn_mma_kernel(const __nv_bfloat16* __restrict__ Qhi,
                const __nv_bfloat16* __restrict__ Qlo,
                const __nv_bfloat16* __restrict__ Khi,
                const __nv_bfloat16* __restrict__ Klo,
                const __nv_bfloat16* __restrict__ Vhi,
                const __nv_bfloat16* __restrict__ Vlo,
                float* __restrict__ O)
{
    extern __shared__ char smem[];
    const uint32_t sb = smem_u32(smem);
    const int tid = threadIdx.x, lane = tid & 31, wid = tid >> 5;
    const int qt = blockIdx.x, h = blockIdx.y, b = blockIdx.z;
    const int q0 = qt * 128;
    const int wm = wid * 16;

    // base pointers (head slice is 64 bf16 = 128B contiguous)
    const __nv_bfloat16* qhb = Qhi + ((size_t)b * SS + q0) * DD + h * HD;
    const __nv_bfloat16* qlb = Qlo + ((size_t)b * SS + q0) * DD + h * HD;
    const __nv_bfloat16* khb = Khi + (size_t)b * SS * DD + h * HD;
    const __nv_bfloat16* klb = Klo + (size_t)b * SS * DD + h * HD;
    const __nv_bfloat16* vhb = Vhi + (size_t)b * SS * DD + h * HD;
    const __nv_bfloat16* vlb = Vlo + (size_t)b * SS * DD + h * HD;

    const int lr = tid >> 3;        // 0..31
    const int lc = tid & 7;         // 16B chunk

    // --- prologue: Q tile (128 rows) + k-tile 0, one cp.async group ---
#pragma unroll
    for (int it = 0; it < 4; it++) {
        int r = lr + it * 32;       // 0..127
        size_t goff = (size_t)r * DD + lc * 8;
        uint32_t soff = sb + (uint32_t)(r * APITCH + lc * 16);
        cp16(soff,         qhb + goff);
        cp16(soff + QTILE, qlb + goff);
    }
#pragma unroll
    for (int it = 0; it < 2; it++) {
        int r = lr + it * 32;       // 0..63
        size_t goff = (size_t)r * DD + lc * 8;
        uint32_t soff = sb + 2 * QTILE + (uint32_t)(r * APITCH + lc * 16);
        cp16(soff,             khb + goff);
        cp16(soff + KTILE,     klb + goff);
        cp16(soff + 2 * KTILE, vhb + goff);
        cp16(soff + 3 * KTILE, vlb + goff);
    }
    CP_COMMIT();

    // fragment address components
    const int g  = lane >> 2;
    const int qd = lane & 3;
    const uint32_t a_off = (uint32_t)((wm + (lane & 7) + ((lane >> 3) & 1) * 8) * APITCH
                                      + ((lane >> 4) & 1) * 16);
    const uint32_t b_off = (uint32_t)(((lane & 7) + ((lane >> 4) & 1) * 8) * APITCH
                                      + ((lane >> 3) & 1) * 16);
    const uint32_t v_off = (uint32_t)(((lane & 7) + ((lane >> 3) & 1) * 8) * APITCH
                                      + ((lane >> 4) & 1) * 16);

    float m0 = -1e30f, m1 = -1e30f, l0 = 0.f, l1 = 0.f;
    float o[8][4];
#pragma unroll
    for (int i = 0; i < 8; i++)
#pragma unroll
        for (int j = 0; j < 4; j++) o[i][j] = 0.f;

    const int row0 = q0 + wm + g;
    const int nkt = 2 * qt + 2;

    for (int kt = 0; kt < nkt; kt++) {
        const uint32_t stage = sb + 2 * QTILE + (uint32_t)(kt & 1) * STAGEA;

        // issue next tile into the other stage, then drain current tile's group
        if (kt + 1 < nkt) {
            const uint32_t nst = sb + 2 * QTILE + (uint32_t)((kt + 1) & 1) * STAGEA;
#pragma unroll
            for (int it = 0; it < 2; it++) {
                int r = lr + it * 32;
                size_t goff = (size_t)((kt + 1) * 64 + r) * DD + lc * 8;
                uint32_t soff = nst + (uint32_t)(r * APITCH + lc * 16);
                cp16(soff,             khb + goff);
                cp16(soff + KTILE,     klb + goff);
                cp16(soff + 2 * KTILE, vhb + goff);
                cp16(soff + 3 * KTILE, vlb + goff);
            }
            CP_COMMIT();
            CP_WAIT1();
        } else {
            CP_WAIT0();
        }
        __syncthreads();

        if (kt * 64 <= q0 + wm + 15) {
            // --- S = Q K^T (bf16x3) ---
            float s[8][4];
#pragma unroll
            for (int i = 0; i < 8; i++)
#pragma unroll
                for (int j = 0; j < 4; j++) s[i][j] = 0.f;

#pragma unroll
            for (int ks = 0; ks < 4; ks++) {
                uint32_t qh[4], ql[4];
                uint32_t qa = sb + a_off + ks * 32;
                ldsm_x4(qa, qh);
                ldsm_x4(qa + QTILE, ql);
#pragma unroll
                for (int np = 0; np < 4; np++) {
                    uint32_t kh[4], kl[4];
                    uint32_t ka = stage + b_off + np * 16 * APITCH + ks * 32;
                    ldsm_x4(ka, kh);
                    ldsm_x4(ka + KTILE, kl);
#pragma unroll
                    for (int hh = 0; hh < 2; hh++) {
                        float* d = s[np * 2 + hh];
                        mma16816(d, qh, &kh[hh * 2]);
                        mma16816(d, qh, &kl[hh * 2]);
                        mma16816(d, ql, &kh[hh * 2]);
                    }
                }
            }

            // --- scale + causal mask ---
            const int kbase0 = kt * 64;
            if (kbase0 + 63 > row0) {
#pragma unroll
                for (int nt = 0; nt < 8; nt++) {
                    int col = kbase0 + nt * 8 + qd * 2;
                    s[nt][0] = (col     <= row0)     ? s[nt][0] * 0.125f : -1e30f;
                    s[nt][1] = (col + 1 <= row0)     ? s[nt][1] * 0.125f : -1e30f;
                    s[nt][2] = (col     <= row0 + 8) ? s[nt][2] * 0.125f : -1e30f;
                    s[nt][3] = (col + 1 <= row0 + 8) ? s[nt][3] * 0.125f : -1e30f;
                }
            } else {
#pragma unroll
                for (int nt = 0; nt < 8; nt++) {
                    s[nt][0] *= 0.125f; s[nt][1] *= 0.125f;
                    s[nt][2] *= 0.125f; s[nt][3] *= 0.125f;
                }
            }

            // --- online softmax (rows g and g+8) ---
            float mx0 = -1e30f, mx1 = -1e30f;
#pragma unroll
            for (int nt = 0; nt < 8; nt++) {
                mx0 = fmaxf(mx0, fmaxf(s[nt][0], s[nt][1]));
                mx1 = fmaxf(mx1, fmaxf(s[nt][2], s[nt][3]));
            }
            mx0 = fmaxf(mx0, __shfl_xor_sync(0xffffffffu, mx0, 1));
            mx0 = fmaxf(mx0, __shfl_xor_sync(0xffffffffu, mx0, 2));
            mx1 = fmaxf(mx1, __shfl_xor_sync(0xffffffffu, mx1, 1));
            mx1 = fmaxf(mx1, __shfl_xor_sync(0xffffffffu, mx1, 2));

            float mn0 = fmaxf(m0, mx0), mn1 = fmaxf(m1, mx1);
            float c0 = __expf(m0 - mn0), c1 = __expf(m1 - mn1);
            m0 = mn0; m1 = mn1;

            float sum0 = 0.f, sum1 = 0.f;
#pragma unroll
            for (int nt = 0; nt < 8; nt++) {
                s[nt][0] = __expf(s[nt][0] - mn0); sum0 += s[nt][0];
                s[nt][1] = __expf(s[nt][1] - mn0); sum0 += s[nt][1];
                s[nt][2] = __expf(s[nt][2] - mn1); sum1 += s[nt][2];
                s[nt][3] = __expf(s[nt][3] - mn1); sum1 += s[nt][3];
            }
            sum0 += __shfl_xor_sync(0xffffffffu, sum0, 1);
            sum0 += __shfl_xor_sync(0xffffffffu, sum0, 2);
            sum1 += __shfl_xor_sync(0xffffffffu, sum1, 1);
            sum1 += __shfl_xor_sync(0xffffffffu, sum1, 2);
            l0 = l0 * c0 + sum0;
            l1 = l1 * c1 + sum1;

#pragma unroll
            for (int nt = 0; nt < 8; nt++) {
                o[nt][0] *= c0; o[nt][1] *= c0;
                o[nt][2] *= c1; o[nt][3] *= c1;
            }

            // --- O += P V (bf16x3; P fragment reuses S accumulator layout) ---
#pragma unroll
            for (int kc = 0; kc < 4; kc++) {
                uint32_t ph[4], pl[4];
                split2(s[2 * kc][0],     s[2 * kc][1],     ph[0], pl[0]);
                split2(s[2 * kc][2],     s[2 * kc][3],     ph[1], pl[1]);
                split2(s[2 * kc + 1][0], s[2 * kc + 1][1], ph[2], pl[2]);
                split2(s[2 * kc + 1][2], s[2 * kc + 1][3], ph[3], pl[3]);
#pragma unroll
                for (int np = 0; np < 4; np++) {
                    uint32_t vh[4], vl[4];
                    uint32_t va = stage + 2 * KTILE + v_off
                                  + kc * 16 * APITCH + np * 32;
                    ldsm_x4_t(va, vh);
                    ldsm_x4_t(va + KTILE, vl);
#pragma unroll
                    for (int hh = 0; hh < 2; hh++) {
                        float* d = o[np * 2 + hh];
                        mma16816(d, ph, &vh[hh * 2]);
                        mma16816(d, ph, &vl[hh * 2]);
                        mma16816(d, pl, &vh[hh * 2]);
                    }
                }
            }
        }
        __syncthreads();
    }

    // --- epilogue: normalize and store ---
    const float inv0 = 1.0f / l0, inv1 = 1.0f / l1;
    float* ob0 = O + ((size_t)b * SS + row0) * DD + h * HD;
    float* ob1 = O + ((size_t)b * SS + row0 + 8) * DD + h * HD;
#pragma unroll
    for (int nt = 0; nt < 8; nt++) {
        int col = nt * 8 + qd * 2;
        *reinterpret_cast<float2*>(&ob0[col]) =
            make_float2(o[nt][0] * inv0, o[nt][1] * inv0);
        *reinterpret_cast<float2*>(&ob1[col]) =
            make_float2(o[nt][2] * inv1, o[nt][3] * inv1);
    }
}

// ---------------- launch ------------------------------------------------------
extern "C" void kernel_launch(void* const* d_in, const int* in_sizes, int n_in,
                              void* d_out, int out_size)
{
    const float* hs     = (const float*)d_in[0];
    const float* WQ_w   = (const float*)d_in[1];
    const float* WQ_b   = (const float*)d_in[2];
    const float* WK_A_w = (const float*)d_in[3];
    const float* WK_B_w = (const float*)d_in[4];
    const float* WK_B_b = (const float*)d_in[5];
    const float* WV_A_w = (const float*)d_in[6];
    const float* WV_B_w = (const float*)d_in[7];
    const float* WV_B_b = (const float*)d_in[8];
    const float* c_w    = (const float*)d_in[9];
    const float* c_b    = (const float*)d_in[10];
    float* out = (float*)d_out;

    float *gatt, *gtmp, *gcpt;
    __nv_bfloat16 *qhi, *qlo, *khi, *klo, *vhi, *vlo;
    cudaGetSymbolAddress((void**)&gatt, g_att);
    cudaGetSymbolAddress((void**)&gtmp, g_tmp);
    cudaGetSymbolAddress((void**)&gcpt, g_cpt);
    cudaGetSymbolAddress((void**)&qhi,  g_qhi);
    cudaGetSymbolAddress((void**)&qlo,  g_qlo);
    cudaGetSymbolAddress((void**)&khi,  g_khi);
    cudaGetSymbolAddress((void**)&klo,  g_klo);
    cudaGetSymbolAddress((void**)&vhi,  g_vhi);
    cudaGetSymbolAddress((void**)&vlo,  g_vlo);

    cudaFuncSetAttribute(hmma_gemm<true, false>,
                         cudaFuncAttributeMaxDynamicSharedMemorySize, HMMA_SMEM);
    cudaFuncSetAttribute(hmma_gemm<true, true>,
                         cudaFuncAttributeMaxDynamicSharedMemorySize, HMMA_SMEM);
    cudaFuncSetAttribute(hmma_gemm<false, false>,
                         cudaFuncAttributeMaxDynamicSharedMemorySize, HMMA_SMEM);
    cudaFuncSetAttribute(attn_mma_kernel,
                         cudaFuncAttributeMaxDynamicSharedMemorySize, ATT_SMEM);

    dim3 blk(256);

    // c_proj: [K,N] -> [N,K] once
    transpose_kernel<<<dim3(DD / 32, DD / 32), blk>>>(c_w, gcpt, DD, DD);

    // Q = hs @ WQ^T + b  -> split bf16
    hmma_gemm<true, true><<<dim3(DD / 128, MTOT / 128), blk, HMMA_SMEM>>>(
        hs, WQ_w, WQ_b, nullptr, qhi, qlo, MTOT, DD, DD);
    // tmp = hs @ WK_A^T ; K = tmp @ WK_B^T + b -> split bf16
    hmma_gemm<false, false><<<dim3(RR / 128, MTOT / 128), blk, HMMA_SMEM>>>(
        hs, WK_A_w, nullptr, gtmp, nullptr, nullptr, MTOT, RR, DD);
    hmma_gemm<true, true><<<dim3(DD / 128, MTOT / 128), blk, HMMA_SMEM>>>(
        gtmp, WK_B_w, WK_B_b, nullptr, khi, klo, MTOT, DD, RR);
    // tmp = hs @ WV_A^T ; V = tmp @ WV_B^T + b -> split bf16
    hmma_gemm<false, false><<<dim3(RR / 128, MTOT / 128), blk, HMMA_SMEM>>>(
        hs, WV_A_w, nullptr, gtmp, nullptr, nullptr, MTOT, RR, DD);
    hmma_gemm<true, true><<<dim3(DD / 128, MTOT / 128), blk, HMMA_SMEM>>>(
        gtmp, WV_B_w, WV_B_b, nullptr, vhi, vlo, MTOT, DD, RR);

    // causal attention (HMMA flash, cp.async pipelined)
    attn_mma_kernel<<<dim3(SS / 128, HH, BB), blk, ATT_SMEM>>>(
        qhi, qlo, khi, klo, vhi, vlo, gatt);

    // out = att @ c_proj + b   (via transposed weights)
    hmma_gemm<true, false><<<dim3(DD / 128, MTOT / 128), blk, HMMA_SMEM>>>(
        gatt, gcpt, c_b, out, nullptr, nullptr, MTOT, DD, DD);

    (void)in_sizes; (void)n_in; (void)out_size;
}

// round 8
// speedup vs baseline: 2.9834x; 1.0037x over previous
#include <cuda_runtime.h>
#include <cuda_bf16.h>
#include <cstdint>
#include <cstddef>

// Problem dims (fixed)
#define BB 4
#define SS 2048
#define DD 1024
#define HH 16
#define HD 64
#define RR 512
#define MTOT (BB*SS)          // 8192 rows

// ---------------- scratch (device globals: allocation-guard safe) -------------
__device__ float g_att [(size_t)MTOT * DD];   // 32 MB
__device__ float g_tmpk[(size_t)MTOT * RR];   // 16 MB
__device__ float g_tmpv[(size_t)MTOT * RR];   // 16 MB
__device__ float g_cpt [(size_t)DD * DD];     // 4 MB  (c_proj transposed -> [N,K])
// split bf16 Q/K/V (written by projection GEMM epilogues)
__device__ __nv_bfloat16 g_qhi[(size_t)MTOT * DD];
__device__ __nv_bfloat16 g_qlo[(size_t)MTOT * DD];
__device__ __nv_bfloat16 g_khi[(size_t)MTOT * DD];
__device__ __nv_bfloat16 g_klo[(size_t)MTOT * DD];
__device__ __nv_bfloat16 g_vhi[(size_t)MTOT * DD];
__device__ __nv_bfloat16 g_vlo[(size_t)MTOT * DD];

// ---------------- mma.sync helpers (family-stable, OK on compute_103) ----------
__device__ __forceinline__ uint32_t smem_u32(const void* p) {
    uint32_t a;
    asm("{ .reg .u64 t; cvta.to.shared.u64 t, %1; cvt.u32.u64 %0, t; }"
        : "=r"(a) : "l"(p));
    return a;
}

__device__ __forceinline__ void ldsm_x4(uint32_t addr, uint32_t* r) {
    asm volatile("ldmatrix.sync.aligned.m8n8.x4.shared.b16 {%0,%1,%2,%3}, [%4];"
                 : "=r"(r[0]), "=r"(r[1]), "=r"(r[2]), "=r"(r[3]) : "r"(addr));
}
__device__ __forceinline__ void ldsm_x4_t(uint32_t addr, uint32_t* r) {
    asm volatile("ldmatrix.sync.aligned.m8n8.x4.trans.shared.b16 {%0,%1,%2,%3}, [%4];"
                 : "=r"(r[0]), "=r"(r[1]), "=r"(r[2]), "=r"(r[3]) : "r"(addr));
}
__device__ __forceinline__ void mma16816(float* d, const uint32_t* a, const uint32_t* b) {
    asm volatile(
        "mma.sync.aligned.m16n8k16.row.col.f32.bf16.bf16.f32 "
        "{%0,%1,%2,%3}, {%4,%5,%6,%7}, {%8,%9}, {%0,%1,%2,%3};"
        : "+f"(d[0]), "+f"(d[1]), "+f"(d[2]), "+f"(d[3])
        : "r"(a[0]), "r"(a[1]), "r"(a[2]), "r"(a[3]), "r"(b[0]), "r"(b[1]));
}

__device__ __forceinline__ void cp16(uint32_t dst, const void* src) {
    asm volatile("cp.async.cg.shared.global [%0], [%1], 16;"
                 :: "r"(dst), "l"(src) : "memory");
}
#define CP_COMMIT()  asm volatile("cp.async.commit_group;" ::: "memory")
#define CP_WAIT1()   asm volatile("cp.async.wait_group 1;" ::: "memory")
#define CP_WAIT0()   asm volatile("cp.async.wait_group 0;" ::: "memory")

// split a float4 into packed-bf16 hi(8B) and lo(8B)
__device__ __forceinline__ void split_f4(float4 v, uint2& hi, uint2& lo) {
    __nv_bfloat16 h0 = __float2bfloat16(v.x), h1 = __float2bfloat16(v.y);
    __nv_bfloat16 h2 = __float2bfloat16(v.z), h3 = __float2bfloat16(v.w);
    __nv_bfloat16 l0 = __float2bfloat16(v.x - __bfloat162float(h0));
    __nv_bfloat16 l1 = __float2bfloat16(v.y - __bfloat162float(h1));
    __nv_bfloat16 l2 = __float2bfloat16(v.z - __bfloat162float(h2));
    __nv_bfloat16 l3 = __float2bfloat16(v.w - __bfloat162float(h3));
    __nv_bfloat162 hp0(h0, h1), hp1(h2, h3), lp0(l0, l1), lp1(l2, l3);
    hi.x = *reinterpret_cast<uint32_t*>(&hp0);
    hi.y = *reinterpret_cast<uint32_t*>(&hp1);
    lo.x = *reinterpret_cast<uint32_t*>(&lp0);
    lo.y = *reinterpret_cast<uint32_t*>(&lp1);
}

// split a pair of floats into packed bf16 hi / lo
__device__ __forceinline__ void split2(float x, float y, uint32_t& hi, uint32_t& lo) {
    __nv_bfloat16 hx = __float2bfloat16(x), hy = __float2bfloat16(y);
    __nv_bfloat16 lx = __float2bfloat16(x - __bfloat162float(hx));
    __nv_bfloat16 ly = __float2bfloat16(y - __bfloat162float(hy));
    __nv_bfloat162 hp(hx, hy), lp(lx, ly);
    hi = *reinterpret_cast<uint32_t*>(&hp);
    lo = *reinterpret_cast<uint32_t*>(&lp);
}

// ---------------- HMMA bf16x3 GEMM core -----------------------------------------
// C[M,N] = A[M,K] @ B[N,K]^T (+ bias). fp32 in; out fp32 (C) or split bf16 hi/lo.
#define PITCH 80
#define TILE_B (128 * PITCH)
#define STAGE_B (4 * TILE_B)
#define HMMA_SMEM (2 * STAGE_B)

template <bool BIAS, bool SPLITOUT>
__device__ __forceinline__ void
hmma_core(const float* __restrict__ A, const float* __restrict__ B,
          const float* __restrict__ bias, float* __restrict__ C,
          __nv_bfloat16* __restrict__ Chi, __nv_bfloat16* __restrict__ Clo,
          int M, int N, int K)
{
    extern __shared__ char smem[];
    const uint32_t sb = smem_u32(smem);

    const int tid  = threadIdx.x;
    const int lane = tid & 31;
    const int wid  = tid >> 5;
    const int m0 = blockIdx.y * 128, n0 = blockIdx.x * 128;
    const int wm = (wid & 3) * 32;
    const int wn = (wid >> 2) * 64;

    const int lr = tid >> 3;
    const int lq = tid & 7;

    const int a_row = wm + (lane & 7) + ((lane >> 3) & 1) * 8;
    const int a_kb  = ((lane >> 4) & 1) * 16;
    const int b_row = wn + (lane & 7) + ((lane >> 4) & 1) * 8;
    const int b_kb  = ((lane >> 3) & 1) * 16;

    float acc[2][8][4];
#pragma unroll
    for (int i = 0; i < 2; i++)
#pragma unroll
        for (int j = 0; j < 8; j++)
#pragma unroll
            for (int k = 0; k < 4; k++) acc[i][j][k] = 0.f;

    const int NC = K >> 5;

    float4 ra[4], rb[4];
#pragma unroll
    for (int p = 0; p < 4; p++) {
        int row = lr + p * 32;
        ra[p] = *reinterpret_cast<const float4*>(&A[(size_t)(m0 + row) * K + lq * 4]);
        rb[p] = *reinterpret_cast<const float4*>(&B[(size_t)(n0 + row) * K + lq * 4]);
    }
#pragma unroll
    for (int p = 0; p < 4; p++) {
        int row = lr + p * 32;
        uint32_t off = (uint32_t)(row * PITCH + lq * 8);
        uint2 hi, lo;
        split_f4(ra[p], hi, lo);
        *reinterpret_cast<uint2*>(smem + (off))              = hi;
        *reinterpret_cast<uint2*>(smem + (off + TILE_B))     = lo;
        split_f4(rb[p], hi, lo);
        *reinterpret_cast<uint2*>(smem + (off + 2 * TILE_B)) = hi;
        *reinterpret_cast<uint2*>(smem + (off + 3 * TILE_B)) = lo;
    }
    __syncthreads();

    for (int c = 0; c < NC; c++) {
        if (c + 1 < NC) {
            const int kc = (c + 1) << 5;
#pragma unroll
            for (int p = 0; p < 4; p++) {
                int row = lr + p * 32;
                ra[p] = *reinterpret_cast<const float4*>(
                    &A[(size_t)(m0 + row) * K + kc + lq * 4]);
                rb[p] = *reinterpret_cast<const float4*>(
                    &B[(size_t)(n0 + row) * K + kc + lq * 4]);
            }
        }

        const uint32_t st = sb + (uint32_t)(c & 1) * STAGE_B;
#pragma unroll
        for (int ks = 0; ks < 2; ks++) {
            uint32_t ah[2][4], al[2][4];
#pragma unroll
            for (int mt = 0; mt < 2; mt++) {
                uint32_t aaddr = st + (uint32_t)((a_row + mt * 16) * PITCH + a_kb + ks * 32);
                ldsm_x4(aaddr, ah[mt]);
                ldsm_x4(aaddr + TILE_B, al[mt]);
            }
#pragma unroll
            for (int nt2 = 0; nt2 < 4; nt2++) {
                uint32_t bh[4], bl[4];
                uint32_t baddr = st + 2 * TILE_B +
                    (uint32_t)((b_row + nt2 * 16) * PITCH + b_kb + ks * 32);
                ldsm_x4(baddr, bh);
                ldsm_x4(baddr + TILE_B, bl);
#pragma unroll
                for (int mt = 0; mt < 2; mt++) {
#pragma unroll
                    for (int half = 0; half < 2; half++) {
                        float* d = acc[mt][nt2 * 2 + half];
                        mma16816(d, ah[mt], &bh[half * 2]);
                        mma16816(d, ah[mt], &bl[half * 2]);
                        mma16816(d, al[mt], &bh[half * 2]);
                    }
                }
            }
        }

        if (c + 1 < NC) {
            char* so = smem + (size_t)((c + 1) & 1) * STAGE_B;
#pragma unroll
            for (int p = 0; p < 4; p++) {
                int row = lr + p * 32;
                uint32_t off = (uint32_t)(row * PITCH + lq * 8);
                uint2 hi, lo;
                split_f4(ra[p], hi, lo);
                *reinterpret_cast<uint2*>(so + off)              = hi;
                *reinterpret_cast<uint2*>(so + off + TILE_B)     = lo;
                split_f4(rb[p], hi, lo);
                *reinterpret_cast<uint2*>(so + off + 2 * TILE_B) = hi;
                *reinterpret_cast<uint2*>(so + off + 3 * TILE_B) = lo;
            }
        }
        __syncthreads();
    }

    const int g = lane >> 2;
    const int cpair = (lane & 3) * 2;
#pragma unroll
    for (int mt = 0; mt < 2; mt++) {
#pragma unroll
        for (int nt = 0; nt < 8; nt++) {
            int col = n0 + wn + nt * 8 + cpair;
            float bx = 0.f, by = 0.f;
            if (BIAS) { bx = bias[col]; by = bias[col + 1]; }
            int row0 = m0 + wm + mt * 16 + g;
            float x0 = acc[mt][nt][0] + bx, y0 = acc[mt][nt][1] + by;
            float x1 = acc[mt][nt][2] + bx, y1 = acc[mt][nt][3] + by;
            if (SPLITOUT) {
                uint32_t hi, lo;
                size_t o0 = (size_t)row0 * N + col;
                size_t o1 = (size_t)(row0 + 8) * N + col;
                split2(x0, y0, hi, lo);
                *reinterpret_cast<uint32_t*>(Chi + o0) = hi;
                *reinterpret_cast<uint32_t*>(Clo + o0) = lo;
                split2(x1, y1, hi, lo);
                *reinterpret_cast<uint32_t*>(Chi + o1) = hi;
                *reinterpret_cast<uint32_t*>(Clo + o1) = lo;
            } else {
                *reinterpret_cast<float2*>(&C[(size_t)row0 * N + col]) =
                    make_float2(x0, y0);
                *reinterpret_cast<float2*>(&C[(size_t)(row0 + 8) * N + col]) =
                    make_float2(x1, y1);
            }
        }
    }
}

template <bool BIAS, bool SPLITOUT>
__global__ void __launch_bounds__(256)
hmma_gemm(const float* __restrict__ A, const float* __restrict__ B,
          const float* __restrict__ bias, float* __restrict__ C,
          __nv_bfloat16* __restrict__ Chi, __nv_bfloat16* __restrict__ Clo,
          int M, int N, int K)
{
    hmma_core<BIAS, SPLITOUT>(A, B, bias, C, Chi, Clo, M, N, K);
}

// dual fp32-out GEMM (stage-1 K/V low-rank): z selects operand set
__global__ void __launch_bounds__(256)
hmma_gemm_dual_f32(const float* __restrict__ A,
                   const float* __restrict__ B0, const float* __restrict__ B1,
                   float* __restrict__ C0, float* __restrict__ C1,
                   int M, int N, int K)
{
    if (blockIdx.z == 0)
        hmma_core<false, false>(A, B0, nullptr, C0, nullptr, nullptr, M, N, K);
    else
        hmma_core<false, false>(A, B1, nullptr, C1, nullptr, nullptr, M, N, K);
}

// dual split-out GEMM (stage-2 K/V): z selects operand set
__global__ void __launch_bounds__(256)
hmma_gemm_dual_split(const float* __restrict__ A0, const float* __restrict__ A1,
                     const float* __restrict__ B0, const float* __restrict__ B1,
                     const float* __restrict__ bias0, const float* __restrict__ bias1,
                     __nv_bfloat16* __restrict__ C0hi, __nv_bfloat16* __restrict__ C0lo,
                     __nv_bfloat16* __restrict__ C1hi, __nv_bfloat16* __restrict__ C1lo,
                     int M, int N, int K)
{
    if (blockIdx.z == 0)
        hmma_core<true, true>(A0, B0, bias0, nullptr, C0hi, C0lo, M, N, K);
    else
        hmma_core<true, true>(A1, B1, bias1, nullptr, C1hi, C1lo, M, N, K);
}

// ---------------- fp32 transpose (for c_proj: [K,N] -> [N,K]) ------------------
__global__ void __launch_bounds__(256)
transpose_kernel(const float* __restrict__ W, float* __restrict__ out, int K, int N)
{
    __shared__ float t[32][33];
    int k0 = blockIdx.y * 32, n0 = blockIdx.x * 32;
    int tx = threadIdx.x & 31, ty = threadIdx.x >> 5;
#pragma unroll
    for (int i = 0; i < 32; i += 8)
        t[ty + i][tx] = W[(size_t)(k0 + ty + i) * N + n0 + tx];
    __syncthreads();
#pragma unroll
    for (int i = 0; i < 32; i += 8)
        out[(size_t)(n0 + ty + i) * K + k0 + tx] = t[tx][ty + i];
}

// ---------------- HMMA flash attention (bf16 pre-split, cp.async pipelined) ----
// grid (S/128, H, B), 256 threads (8 warps x 16 q-rows), k-tiles of 64, 2 stages.
// __launch_bounds__(256, 2): 2 blocks/SM so one block's softmax overlaps the
// other's MMAs (regs capped at 128; smem 2x110592 <= 228KB).
#define APITCH 144                 // bytes per 64-bf16 row (128B + 16B pad)
#define QTILE (128 * APITCH)       // 18432
#define KTILE (64 * APITCH)        // 9216
#define STAGEA (4 * KTILE)         // Khi,Klo,Vhi,Vlo = 36864
#define ATT_SMEM (2 * QTILE + 2 * STAGEA)   // 110592

__global__ void __launch_bounds__(256, 2)
attn_mma_kernel(const __nv_bfloat16* __restrict__ Qhi,
                const __nv_bfloat16* __restrict__ Qlo,
                const __nv_bfloat16* __restrict__ Khi,
                const __nv_bfloat16* __restrict__ Klo,
                const __nv_bfloat16* __restrict__ Vhi,
                const __nv_bfloat16* __restrict__ Vlo,
                float* __restrict__ O)
{
    extern __shared__ char smem[];
    const uint32_t sb = smem_u32(smem);
    const int tid = threadIdx.x, lane = tid & 31, wid = tid >> 5;
    const int qt = blockIdx.x, h = blockIdx.y, b = blockIdx.z;
    const int q0 = qt * 128;
    const int wm = wid * 16;

    // base pointers (head slice is 64 bf16 = 128B contiguous)
    const __nv_bfloat16* qhb = Qhi + ((size_t)b * SS + q0) * DD + h * HD;
    const __nv_bfloat16* qlb = Qlo + ((size_t)b * SS + q0) * DD + h * HD;
    const __nv_bfloat16* khb = Khi + (size_t)b * SS * DD + h * HD;
    const __nv_bfloat16* klb = Klo + (size_t)b * SS * DD + h * HD;
    const __nv_bfloat16* vhb = Vhi + (size_t)b * SS * DD + h * HD;
    const __nv_bfloat16* vlb = Vlo + (size_t)b * SS * DD + h * HD;

    const int lr = tid >> 3;        // 0..31
    const int lc = tid & 7;         // 16B chunk

    // --- prologue: Q tile (128 rows) + k-tile 0, one cp.async group ---
#pragma unroll
    for (int it = 0; it < 4; it++) {
        int r = lr + it * 32;       // 0..127
        size_t goff = (size_t)r * DD + lc * 8;
        uint32_t soff = sb + (uint32_t)(r * APITCH + lc * 16);
        cp16(soff,         qhb + goff);
        cp16(soff + QTILE, qlb + goff);
    }
#pragma unroll
    for (int it = 0; it < 2; it++) {
        int r = lr + it * 32;       // 0..63
        size_t goff = (size_t)r * DD + lc * 8;
        uint32_t soff = sb + 2 * QTILE + (uint32_t)(r * APITCH + lc * 16);
        cp16(soff,             khb + goff);
        cp16(soff + KTILE,     klb + goff);
        cp16(soff + 2 * KTILE, vhb + goff);
        cp16(soff + 3 * KTILE, vlb + goff);
    }
    CP_COMMIT();

    // fragment address components
    const int g  = lane >> 2;
    const int qd = lane & 3;
    const uint32_t a_off = (uint32_t)((wm + (lane & 7) + ((lane >> 3) & 1) * 8) * APITCH
                                      + ((lane >> 4) & 1) * 16);
    const uint32_t b_off = (uint32_t)(((lane & 7) + ((lane >> 4) & 1) * 8) * APITCH
                                      + ((lane >> 3) & 1) * 16);
    const uint32_t v_off = (uint32_t)(((lane & 7) + ((lane >> 3) & 1) * 8) * APITCH
                                      + ((lane >> 4) & 1) * 16);

    float m0 = -1e30f, m1 = -1e30f, l0 = 0.f, l1 = 0.f;
    float o[8][4];
#pragma unroll
    for (int i = 0; i < 8; i++)
#pragma unroll
        for (int j = 0; j < 4; j++) o[i][j] = 0.f;

    const int row0 = q0 + wm + g;
    const int nkt = 2 * qt + 2;

    for (int kt = 0; kt < nkt; kt++) {
        const uint32_t stage = sb + 2 * QTILE + (uint32_t)(kt & 1) * STAGEA;

        // issue next tile into the other stage, then drain current tile's group
        if (kt + 1 < nkt) {
            const uint32_t nst = sb + 2 * QTILE + (uint32_t)((kt + 1) & 1) * STAGEA;
#pragma unroll
            for (int it = 0; it < 2; it++) {
                int r = lr + it * 32;
                size_t goff = (size_t)((kt + 1) * 64 + r) * DD + lc * 8;
                uint32_t soff = nst + (uint32_t)(r * APITCH + lc * 16);
                cp16(soff,             khb + goff);
                cp16(soff + KTILE,     klb + goff);
                cp16(soff + 2 * KTILE, vhb + goff);
                cp16(soff + 3 * KTILE, vlb + goff);
            }
            CP_COMMIT();
            CP_WAIT1();
        } else {
            CP_WAIT0();
        }
        __syncthreads();

        if (kt * 64 <= q0 + wm + 15) {
            // --- S = Q K^T (bf16x3) ---
            float s[8][4];
#pragma unroll
            for (int i = 0; i < 8; i++)
#pragma unroll
                for (int j = 0; j < 4; j++) s[i][j] = 0.f;

#pragma unroll
            for (int ks = 0; ks < 4; ks++) {
                uint32_t qh[4], ql[4];
                uint32_t qa = sb + a_off + ks * 32;
                ldsm_x4(qa, qh);
                ldsm_x4(qa + QTILE, ql);
#pragma unroll
                for (int np = 0; np < 4; np++) {
                    uint32_t kh[4], kl[4];
                    uint32_t ka = stage + b_off + np * 16 * APITCH + ks * 32;
                    ldsm_x4(ka, kh);
                    ldsm_x4(ka + KTILE, kl);
#pragma unroll
                    for (int hh = 0; hh < 2; hh++) {
                        float* d = s[np * 2 + hh];
                        mma16816(d, qh, &kh[hh * 2]);
                        mma16816(d, qh, &kl[hh * 2]);
                        mma16816(d, ql, &kh[hh * 2]);
                    }
                }
            }

            // --- scale + causal mask ---
            const int kbase0 = kt * 64;
            if (kbase0 + 63 > row0) {
#pragma unroll
                for (int nt = 0; nt < 8; nt++) {
                    int col = kbase0 + nt * 8 + qd * 2;
                    s[nt][0] = (col     <= row0)     ? s[nt][0] * 0.125f : -1e30f;
                    s[nt][1] = (col + 1 <= row0)     ? s[nt][1] * 0.125f : -1e30f;
                    s[nt][2] = (col     <= row0 + 8) ? s[nt][2] * 0.125f : -1e30f;
                    s[nt][3] = (col + 1 <= row0 + 8) ? s[nt][3] * 0.125f : -1e30f;
                }
            } else {
#pragma unroll
                for (int nt = 0; nt < 8; nt++) {
                    s[nt][0] *= 0.125f; s[nt][1] *= 0.125f;
                    s[nt][2] *= 0.125f; s[nt][3] *= 0.125f;
                }
            }

            // --- online softmax (rows g and g+8) ---
            float mx0 = -1e30f, mx1 = -1e30f;
#pragma unroll
            for (int nt = 0; nt < 8; nt++) {
                mx0 = fmaxf(mx0, fmaxf(s[nt][0], s[nt][1]));
                mx1 = fmaxf(mx1, fmaxf(s[nt][2], s[nt][3]));
            }
            mx0 = fmaxf(mx0, __shfl_xor_sync(0xffffffffu, mx0, 1));
            mx0 = fmaxf(mx0, __shfl_xor_sync(0xffffffffu, mx0, 2));
            mx1 = fmaxf(mx1, __shfl_xor_sync(0xffffffffu, mx1, 1));
            mx1 = fmaxf(mx1, __shfl_xor_sync(0xffffffffu, mx1, 2));

            float mn0 = fmaxf(m0, mx0), mn1 = fmaxf(m1, mx1);
            float c0 = __expf(m0 - mn0), c1 = __expf(m1 - mn1);
            m0 = mn0; m1 = mn1;

            float sum0 = 0.f, sum1 = 0.f;
#pragma unroll
            for (int nt = 0; nt < 8; nt++) {
                s[nt][0] = __expf(s[nt][0] - mn0); sum0 += s[nt][0];
                s[nt][1] = __expf(s[nt][1] - mn0); sum0 += s[nt][1];
                s[nt][2] = __expf(s[nt][2] - mn1); sum1 += s[nt][2];
                s[nt][3] = __expf(s[nt][3] - mn1); sum1 += s[nt][3];
            }
            sum0 += __shfl_xor_sync(0xffffffffu, sum0, 1);
            sum0 += __shfl_xor_sync(0xffffffffu, sum0, 2);
            sum1 += __shfl_xor_sync(0xffffffffu, sum1, 1);
            sum1 += __shfl_xor_sync(0xffffffffu, sum1, 2);
            l0 = l0 * c0 + sum0;
            l1 = l1 * c1 + sum1;

#pragma unroll
            for (int nt = 0; nt < 8; nt++) {
                o[nt][0] *= c0; o[nt][1] *= c0;
                o[nt][2] *= c1; o[nt][3] *= c1;
            }

            // --- O += P V (bf16x3; P fragment reuses S accumulator layout) ---
#pragma unroll
            for (int kc = 0; kc < 4; kc++) {
                uint32_t ph[4], pl[4];
                split2(s[2 * kc][0],     s[2 * kc][1],     ph[0], pl[0]);
                split2(s[2 * kc][2],     s[2 * kc][3],     ph[1], pl[1]);
                split2(s[2 * kc + 1][0], s[2 * kc + 1][1], ph[2], pl[2]);
                split2(s[2 * kc + 1][2], s[2 * kc + 1][3], ph[3], pl[3]);
#pragma unroll
                for (int np = 0; np < 4; np++) {
                    uint32_t vh[4], vl[4];
                    uint32_t va = stage + 2 * KTILE + v_off
                                  + kc * 16 * APITCH + np * 32;
                    ldsm_x4_t(va, vh);
                    ldsm_x4_t(va + KTILE, vl);
#pragma unroll
                    for (int hh = 0; hh < 2; hh++) {
                        float* d = o[np * 2 + hh];
                        mma16816(d, ph, &vh[hh * 2]);
                        mma16816(d, ph, &vl[hh * 2]);
                        mma16816(d, pl, &vh[hh * 2]);
                    }
                }
            }
        }
        __syncthreads();
    }

    // --- epilogue: normalize and store ---
    const float inv0 = 1.0f / l0, inv1 = 1.0f / l1;
    float* ob0 = O + ((size_t)b * SS + row0) * DD + h * HD;
    float* ob1 = O + ((size_t)b * SS + row0 + 8) * DD + h * HD;
#pragma unroll
    for (int nt = 0; nt < 8; nt++) {
        int col = nt * 8 + qd * 2;
        *reinterpret_cast<float2*>(&ob0[col]) =
            make_float2(o[nt][0] * inv0, o[nt][1] * inv0);
        *reinterpret_cast<float2*>(&ob1[col]) =
            make_float2(o[nt][2] * inv1, o[nt][3] * inv1);
    }
}

// ---------------- launch ------------------------------------------------------
extern "C" void kernel_launch(void* const* d_in, const int* in_sizes, int n_in,
                              void* d_out, int out_size)
{
    const float* hs     = (const float*)d_in[0];
    const float* WQ_w   = (const float*)d_in[1];
    const float* WQ_b   = (const float*)d_in[2];
    const float* WK_A_w = (const float*)d_in[3];
    const float* WK_B_w = (const float*)d_in[4];
    const float* WK_B_b = (const float*)d_in[5];
    const float* WV_A_w = (const float*)d_in[6];
    const float* WV_B_w = (const float*)d_in[7];
    const float* WV_B_b = (const float*)d_in[8];
    const float* c_w    = (const float*)d_in[9];
    const float* c_b    = (const float*)d_in[10];
    float* out = (float*)d_out;

    float *gatt, *gtmpk, *gtmpv, *gcpt;
    __nv_bfloat16 *qhi, *qlo, *khi, *klo, *vhi, *vlo;
    cudaGetSymbolAddress((void**)&gatt,  g_att);
    cudaGetSymbolAddress((void**)&gtmpk, g_tmpk);
    cudaGetSymbolAddress((void**)&gtmpv, g_tmpv);
    cudaGetSymbolAddress((void**)&gcpt,  g_cpt);
    cudaGetSymbolAddress((void**)&qhi,   g_qhi);
    cudaGetSymbolAddress((void**)&qlo,   g_qlo);
    cudaGetSymbolAddress((void**)&khi,   g_khi);
    cudaGetSymbolAddress((void**)&klo,   g_klo);
    cudaGetSymbolAddress((void**)&vhi,   g_vhi);
    cudaGetSymbolAddress((void**)&vlo,   g_vlo);

    cudaFuncSetAttribute(hmma_gemm<true, false>,
                         cudaFuncAttributeMaxDynamicSharedMemorySize, HMMA_SMEM);
    cudaFuncSetAttribute(hmma_gemm<true, true>,
                         cudaFuncAttributeMaxDynamicSharedMemorySize, HMMA_SMEM);
    cudaFuncSetAttribute(hmma_gemm_dual_f32,
                         cudaFuncAttributeMaxDynamicSharedMemorySize, HMMA_SMEM);
    cudaFuncSetAttribute(hmma_gemm_dual_split,
                         cudaFuncAttributeMaxDynamicSharedMemorySize, HMMA_SMEM);
    cudaFuncSetAttribute(attn_mma_kernel,
                         cudaFuncAttributeMaxDynamicSharedMemorySize, ATT_SMEM);

    dim3 blk(256);

    // c_proj: [K,N] -> [N,K] once
    transpose_kernel<<<dim3(DD / 32, DD / 32), blk>>>(c_w, gcpt, DD, DD);

    // Q = hs @ WQ^T + b  -> split bf16
    hmma_gemm<true, true><<<dim3(DD / 128, MTOT / 128), blk, HMMA_SMEM>>>(
        hs, WQ_w, WQ_b, nullptr, qhi, qlo, MTOT, DD, DD);

    // stage-1 low-rank: tmp_k = hs @ WK_A^T, tmp_v = hs @ WV_A^T  (one launch)
    hmma_gemm_dual_f32<<<dim3(RR / 128, MTOT / 128, 2), blk, HMMA_SMEM>>>(
        hs, WK_A_w, WV_A_w, gtmpk, gtmpv, MTOT, RR, DD);

    // stage-2: K = tmp_k @ WK_B^T + b, V = tmp_v @ WV_B^T + b  (one launch, split out)
    hmma_gemm_dual_split<<<dim3(DD / 128, MTOT / 128, 2), blk, HMMA_SMEM>>>(
        gtmpk, gtmpv, WK_B_w, WV_B_w, WK_B_b, WV_B_b,
        khi, klo, vhi, vlo, MTOT, DD, RR);

    // causal attention (HMMA flash, cp.async pipelined, 2 blocks/SM)
    attn_mma_kernel<<<dim3(SS / 128, HH, BB), blk, ATT_SMEM>>>(
        qhi, qlo, khi, klo, vhi, vlo, gatt);

    // out = att @ c_proj + b   (via transposed weights)
    hmma_gemm<true, false><<<dim3(DD / 128, MTOT / 128), blk, HMMA_SMEM>>>(
        gatt, gcpt, c_b, out, nullptr, nullptr, MTOT, DD, DD);

    (void)in_sizes; (void)n_in; (void)out_size;
}